// round 5
// baseline (speedup 1.0000x reference)
#include <cuda_runtime.h>
#include <math.h>
#include <string.h>

#define HQ    16
#define GRP   4
#define TOPK  16
#define DQK   192
#define DV    128
#define QT    64
#define THREADS 512
#define KTP   66     // EVEN: float2 kT loads stay 8B-aligned
#define PPAD  65
#define NBITS 32
#define SMSCALE 0.07216878364870322f

// smem floats:
//  qT   [192][64] = 12288   (transposed Q: adjacent queries form native f32x2 pairs)
//  kT   [192][66] = 12672
//  vs   2x[64][128] = 16384
//  ps   [64][65]  =  4160
//  ms/ls/scl [64] each = 192
//  selm [64]u, jlist[33], njs
#define SMEM_FLOATS (12288 + 12672 + 16384 + 4160 + 192 + 64 + 33 + 1)
#define SMEM_BYTES  (SMEM_FLOATS * 4)

__device__ __forceinline__ void ffma2(float2& d, const float2 a, const float2 b) {
    unsigned long long ua, ub;
    memcpy(&ua, &a, 8); memcpy(&ub, &b, 8);
    unsigned long long* pd = reinterpret_cast<unsigned long long*>(&d);
    asm("fma.rn.f32x2 %0, %1, %2, %0;" : "+l"(*pd) : "l"(ua), "l"(ub));
}
__device__ __forceinline__ void fmul2(float2& d, const float2 b) {
    unsigned long long ub;
    memcpy(&ub, &b, 8);
    unsigned long long* pd = reinterpret_cast<unsigned long long*>(&d);
    asm("mul.rn.f32x2 %0, %0, %1;" : "+l"(*pd) : "l"(ub));
}
__device__ __forceinline__ float2 dup2(float x) {
    float2 r;
    unsigned long long* pr = reinterpret_cast<unsigned long long*>(&r);
    asm("mov.b64 %0, {%1, %1};" : "=l"(*pr) : "f"(x));
    return r;
}

__global__ __launch_bounds__(THREADS, 1)
void selattn_kernel(const float* __restrict__ q, const float* __restrict__ k,
                    const float* __restrict__ v, const int* __restrict__ sidx,
                    const int* __restrict__ slp, float* __restrict__ out) {
    extern __shared__ float sh[];
    float* qT  = sh;                          // [192][64]
    float* kT  = qT + DQK * QT;               // [192][66]
    float* vsb[2]; vsb[0] = kT + DQK * KTP; vsb[1] = vsb[0] + 64 * DV;
    float* ps  = vsb[1] + 64 * DV;            // [64][65]
    float* ms  = ps + 64 * PPAD;              // [64]
    float* ls  = ms + 64;                     // [64]
    float* scl = ls + 64;                     // [64]
    unsigned* selm = (unsigned*)(scl + 64);   // [64]
    int* jlist = (int*)(selm + 64);           // [33]
    int* njsp  = jlist + 33;

    const int S    = slp ? slp[0] : 2048;
    const int qt   = blockIdx.x;
    const int h    = blockIdx.y;
    const int g    = h >> 2;
    const int t0   = qt * QT;
    const int seq0 = (t0 / S) * S;
    const int tid  = threadIdx.x;
    const int lane = tid & 31;
    const int w    = tid >> 5;

    // ---- prologue: selection masks ----
    if (tid < QT) { selm[tid] = 0u; ms[tid] = -1e30f; ls[tid] = 0.0f; }
    __syncthreads();
    for (int f = tid; f < QT * TOPK; f += THREADS) {
        int qi = f >> 4, kk = f & 15;
        int b = sidx[(size_t)(t0 + qi) * (GRP * TOPK) + g * TOPK + kk] & 31;
        atomicOr(&selm[qi], 1u << b);
    }
    __syncthreads();
    if (tid < QT) {
        int tq = (t0 + tid) - seq0;
        int bt = tq >> 6;
        unsigned causal = (bt >= 31) ? 0xffffffffu : ((1u << (bt + 1)) - 1u);
        selm[tid] &= causal;
    }
    __syncthreads();
    if (tid == 0) {
        unsigned u = 0;
        #pragma unroll
        for (int i = 0; i < QT; i++) u |= selm[i];
        int n = 0;
        for (int j = 0; j < NBITS; j++)
            if ((u >> j) & 1u) jlist[n++] = j;
        *njsp = n;
    }
    // ---- build qT (transposed; scattered LDG once, conflict-free STS) ----
    for (int f = tid; f < QT * (DQK / 4); f += THREADS) {
        int qi = f & 63, dq = f >> 6;
        float4 gq = *(const float4*)(q + (size_t)(t0 + qi) * HQ * DQK
                                       + (size_t)h * DQK + 4 * dq);
        qT[(4 * dq + 0) * QT + qi] = gq.x;
        qT[(4 * dq + 1) * QT + qi] = gq.y;
        qT[(4 * dq + 2) * QT + qi] = gq.z;
        qT[(4 * dq + 3) * QT + qi] = gq.w;
    }
    __syncthreads();
    const int njs = *njsp;

    // ---- fill(jn, bn): plain LDG+STS (R3-proven) ----
    auto do_fill = [&](int jn, int bn) {
        const float* kblk = k + ((size_t)(seq0 + jn * 64) * HQ + h) * DQK;
        for (int f = tid; f < 64 * DQK; f += THREADS) {
            int s = f / DQK, d = f - s * DQK;
            kT[d * KTP + s] = kblk[(size_t)s * HQ * DQK + d];
        }
        const float* vblk = v + ((size_t)(seq0 + jn * 64) * HQ + h) * DV;
        float* vd = vsb[bn];
        for (int f = tid; f < 64 * (DV / 4); f += THREADS) {
            int s = f >> 5, c = f & 31;
            ((float4*)vd)[s * 32 + c] =
                ((const float4*)vblk)[(size_t)s * HQ * (DV / 4) + c];
        }
    };

    if (njs > 0) do_fill(jlist[0], 0);
    __syncthreads();

    // PV static ownership: warp = 16q x 32d, lane = 1q x 16d
    const int pvq = (w & 3) * 16 + (lane & 15);
    const int pvd = (w >> 2) * 32 + (lane >> 4) * 16;
    float2 acc[8];
    #pragma unroll
    for (int i = 0; i < 8; i++) acc[i] = make_float2(0.0f, 0.0f);

    const int qbase = w * 4;    // score: warp owns queries qbase..qbase+3 (2 pairs)

    for (int ii = 0; ii < njs; ii++) {
        const int b = ii & 1;
        const int j = jlist[ii];

        // ================= Phase A: dense paired score =================
        {
            float2 a00 = make_float2(0.f, 0.f);  // pair0 (q0,q1), kv0
            float2 a01 = make_float2(0.f, 0.f);  // pair0, kv1
            float2 a10 = make_float2(0.f, 0.f);  // pair1 (q2,q3), kv0
            float2 a11 = make_float2(0.f, 0.f);  // pair1, kv1
            const float* kr = kT + 2 * lane;
            const float* qr = qT + qbase;
            #pragma unroll 4
            for (int d = 0; d < DQK; d += 4) {
                #pragma unroll
                for (int i = 0; i < 4; i++) {
                    const float2 kv = *(const float2*)(kr + (d + i) * KTP);
                    const float4 qv = *(const float4*)(qr + (d + i) * QT);
                    const float2 k0 = dup2(kv.x);
                    const float2 k1 = dup2(kv.y);
                    const float2 p0 = make_float2(qv.x, qv.y);
                    const float2 p1 = make_float2(qv.z, qv.w);
                    ffma2(a00, p0, k0);
                    ffma2(a01, p0, k1);
                    ffma2(a10, p1, k0);
                    ffma2(a11, p1, k1);
                }
            }
            const float sc0[4] = {a00.x, a00.y, a10.x, a10.y};
            const float sc1[4] = {a01.x, a01.y, a11.x, a11.y};
            const int sg = j * 64 + 2 * lane;
            #pragma unroll
            for (int u = 0; u < 4; u++) {
                const int qi = qbase + u;
                const int tq = t0 + qi - seq0;
                const bool sel = (selm[qi] >> j) & 1u;
                const bool c0 = sel && (sg     <= tq);
                const bool c1 = sel && (sg + 1 <= tq);
                float a0 = c0 ? sc0[u] * SMSCALE : -1e30f;
                float a1 = c1 ? sc1[u] * SMSCALE : -1e30f;
                float mx = fmaxf(a0, a1);
                #pragma unroll
                for (int o = 16; o; o >>= 1)
                    mx = fmaxf(mx, __shfl_xor_sync(0xffffffffu, mx, o));
                const float mo = ms[qi];
                const float mn = fmaxf(mo, mx);
                const float p0 = c0 ? __expf(a0 - mn) : 0.0f;
                const float p1 = c1 ? __expf(a1 - mn) : 0.0f;
                float r = p0 + p1;
                #pragma unroll
                for (int o = 16; o; o >>= 1)
                    r += __shfl_xor_sync(0xffffffffu, r, o);
                ps[(2 * lane)     * PPAD + qi] = p0;
                ps[(2 * lane + 1) * PPAD + qi] = p1;
                if (lane == 0) {
                    const float sv = __expf(mo - mn);   // mx==-1e30 -> mn==mo -> sv=1
                    scl[qi] = sv;
                    ls[qi] = ls[qi] * sv + r;
                    ms[qi] = mn;
                }
            }
        }
        __syncthreads();

        // ============== Phase B: fill(j+1) + PV(j) ==============
        if (ii + 1 < njs) do_fill(jlist[ii + 1], b ^ 1);
        {
            const float sc = scl[pvq];
            const float2 scp = make_float2(sc, sc);
            #pragma unroll
            for (int i = 0; i < 8; i++) fmul2(acc[i], scp);
            const float* vbase = vsb[b] + pvd;
            #pragma unroll 4
            for (int s = 0; s < 64; s++) {
                const float p = ps[s * PPAD + pvq];
                const float2 pp = make_float2(p, p);
                const float4* vp = (const float4*)(vbase + s * DV);
                const float4 b0 = vp[0], b1 = vp[1], b2 = vp[2], b3 = vp[3];
                ffma2(acc[0], make_float2(b0.x, b0.y), pp);
                ffma2(acc[1], make_float2(b0.z, b0.w), pp);
                ffma2(acc[2], make_float2(b1.x, b1.y), pp);
                ffma2(acc[3], make_float2(b1.z, b1.w), pp);
                ffma2(acc[4], make_float2(b2.x, b2.y), pp);
                ffma2(acc[5], make_float2(b2.z, b2.w), pp);
                ffma2(acc[6], make_float2(b3.x, b3.y), pp);
                ffma2(acc[7], make_float2(b3.z, b3.w), pp);
            }
        }
        __syncthreads();
    }

    // ---- finalize ----
    const float invl = 1.0f / ls[pvq];
    float* op = out + (size_t)(t0 + pvq) * (HQ * DV) + (size_t)h * DV + pvd;
    float4 o0, o1, o2, o3;
    o0.x = acc[0].x * invl; o0.y = acc[0].y * invl; o0.z = acc[1].x * invl; o0.w = acc[1].y * invl;
    o1.x = acc[2].x * invl; o1.y = acc[2].y * invl; o1.z = acc[3].x * invl; o1.w = acc[3].y * invl;
    o2.x = acc[4].x * invl; o2.y = acc[4].y * invl; o2.z = acc[5].x * invl; o2.w = acc[5].y * invl;
    o3.x = acc[6].x * invl; o3.y = acc[6].y * invl; o3.z = acc[7].x * invl; o3.w = acc[7].y * invl;
    *(float4*)(op)      = o0;
    *(float4*)(op + 4)  = o1;
    *(float4*)(op + 8)  = o2;
    *(float4*)(op + 12) = o3;
}

extern "C" void kernel_launch(void* const* d_in, const int* in_sizes, int n_in,
                              void* d_out, int out_size) {
    const float* q   = (const float*)d_in[0];
    const float* k   = (const float*)d_in[1];
    const float* v   = (const float*)d_in[2];
    const int*   idx = (const int*)d_in[3];
    const int*   slp = (n_in >= 6) ? (const int*)d_in[5] : nullptr;
    float* out = (float*)d_out;

    const int T = in_sizes[0] / (HQ * DQK);

    static bool attr_set = false;
    if (!attr_set) {
        cudaFuncSetAttribute(selattn_kernel,
                             cudaFuncAttributeMaxDynamicSharedMemorySize, SMEM_BYTES);
        attr_set = true;
    }

    dim3 grid(T / QT, HQ);
    selattn_kernel<<<grid, THREADS, SMEM_BYTES>>>(q, k, v, idx, slp, out);
}

// round 6
// speedup vs baseline: 1.1309x; 1.1309x over previous
#include <cuda_runtime.h>
#include <math.h>
#include <string.h>

#define HQ    16
#define GRP   4
#define TOPK  16
#define DQK   192
#define DV    128
#define QT    64
#define THREADS 512
#define KTP   66     // EVEN: float2 kT loads stay 8B-aligned
#define PPAD  65
#define NBITS 32
#define SMSCALE 0.07216878364870322f

// smem floats:
//  qs   [65][192] = 12480  (row 64 = dummy query, zeroed)
//  kT   [192][66] = 12672  (single buffer)
//  vs   2x[64][128] = 16384
//  ps   2x[64][65]  = 8320
//  ms/ls [65], scl 2x[65]
//  selm[64]u, list 2x[72]i, nsel[2], jlist[33], njs
#define SMEM_FLOATS (12480 + 12672 + 16384 + 8320 + 65 + 65 + 130 + 64 + 144 + 2 + 33 + 1)
#define SMEM_BYTES  (SMEM_FLOATS * 4)

__device__ __forceinline__ void ffma2(float2& d, const float2 a, const float2 b) {
    unsigned long long ua, ub;
    memcpy(&ua, &a, 8); memcpy(&ub, &b, 8);
    unsigned long long* pd = reinterpret_cast<unsigned long long*>(&d);
    asm("fma.rn.f32x2 %0, %1, %2, %0;" : "+l"(*pd) : "l"(ua), "l"(ub));
}
__device__ __forceinline__ void fmul2(float2& d, const float2 b) {
    unsigned long long ub;
    memcpy(&ub, &b, 8);
    unsigned long long* pd = reinterpret_cast<unsigned long long*>(&d);
    asm("mul.rn.f32x2 %0, %0, %1;" : "+l"(*pd) : "l"(ub));
}

__global__ __launch_bounds__(THREADS, 1)
void selattn_kernel(const float* __restrict__ q, const float* __restrict__ k,
                    const float* __restrict__ v, const int* __restrict__ sidx,
                    const int* __restrict__ slp, float* __restrict__ out) {
    extern __shared__ float sh[];
    float* qs  = sh;                          // [65][192]
    float* kT  = qs + 65 * DQK;               // [192][66]
    float* vsb[2]; vsb[0] = kT + DQK * KTP; vsb[1] = vsb[0] + 64 * DV;
    float* psb[2]; psb[0] = vsb[1] + 64 * DV; psb[1] = psb[0] + 64 * PPAD;
    float* ms  = psb[1] + 64 * PPAD;          // [65]
    float* ls  = ms + 65;                     // [65]
    float* sclb[2]; sclb[0] = ls + 65; sclb[1] = sclb[0] + 65;
    unsigned* selm = (unsigned*)(sclb[1] + 65);   // [64]
    int* listb[2]; listb[0] = (int*)(selm + 64); listb[1] = listb[0] + 72;
    int* nselb  = listb[1] + 72;              // [2]
    int* jlist  = nselb + 2;                  // [33]
    int* njsp   = jlist + 33;

    const int S    = slp ? slp[0] : 2048;
    const int qt   = blockIdx.x;
    const int h    = blockIdx.y;
    const int g    = h >> 2;
    const int t0   = qt * QT;
    const int seq0 = (t0 / S) * S;
    const int tid  = threadIdx.x;
    const int lane = tid & 31;
    const int w    = tid >> 5;

    // ---- prologue: Q tile, selection masks, active-block list ----
    for (int f = tid; f < QT * (DQK / 4); f += THREADS) {
        int qi = f / (DQK / 4), dq = f % (DQK / 4);
        ((float4*)qs)[qi * (DQK / 4) + dq] =
            ((const float4*)(q + (size_t)(t0 + qi) * HQ * DQK + (size_t)h * DQK))[dq];
    }
    if (tid < DQK) qs[QT * DQK + tid] = 0.0f;    // dummy query row
    if (tid < QT)  selm[tid] = 0u;
    if (tid < 65) { ms[tid] = -1e30f; ls[tid] = 0.0f; }
    __syncthreads();

    for (int f = tid; f < QT * TOPK; f += THREADS) {
        int qi = f >> 4, kk = f & 15;
        int b = sidx[(size_t)(t0 + qi) * (GRP * TOPK) + g * TOPK + kk] & 31;
        atomicOr(&selm[qi], 1u << b);
    }
    __syncthreads();
    if (tid < QT) {
        int tq = (t0 + tid) - seq0;
        int bt = tq >> 6;
        unsigned causal = (bt >= 31) ? 0xffffffffu : ((1u << (bt + 1)) - 1u);
        selm[tid] &= causal;
    }
    __syncthreads();
    if (tid == 0) {
        unsigned u = 0;
        #pragma unroll
        for (int i = 0; i < QT; i++) u |= selm[i];
        int n = 0;
        for (int j = 0; j < NBITS; j++)
            if ((u >> j) & 1u) jlist[n++] = j;
        *njsp = n;
    }
    __syncthreads();
    const int njs = *njsp;

    // ---- fill(jn, bn): plain LDG+STS kT transpose, float4 V, zero ps, scl, compact ----
    auto do_fill = [&](int jn, int bn) {
        const float* kblk = k + ((size_t)(seq0 + jn * 64) * HQ + h) * DQK;
        for (int f = tid; f < 64 * DQK; f += THREADS) {
            int s = f / DQK, d = f - s * DQK;
            kT[d * KTP + s] = kblk[(size_t)s * HQ * DQK + d];
        }
        const float* vblk = v + ((size_t)(seq0 + jn * 64) * HQ + h) * DV;
        float* vd = vsb[bn];
        for (int f = tid; f < 64 * (DV / 4); f += THREADS) {
            int s = f >> 5, c = f & 31;
            ((float4*)vd)[s * 32 + c] =
                ((const float4*)vblk)[(size_t)s * HQ * (DV / 4) + c];
        }
        float2* pz = (float2*)psb[bn];
        for (int f = tid; f < (64 * PPAD) / 2; f += THREADS)
            pz[f] = make_float2(0.f, 0.f);
        if (tid < 65) sclb[bn][tid] = 1.0f;
        if (w == 0) {
            int* lb = listb[bn];
            lb[lane] = 64; lb[lane + 32] = 64;
            if (lane < 8) lb[64 + lane] = 64;
            __syncwarp();
            bool a0 = (selm[lane]      >> jn) & 1u;
            bool a1 = (selm[lane + 32] >> jn) & 1u;
            unsigned b0 = __ballot_sync(0xffffffffu, a0);
            unsigned b1 = __ballot_sync(0xffffffffu, a1);
            unsigned lt = (1u << lane) - 1u;
            if (a0) lb[__popc(b0 & lt)] = lane;
            if (a1) lb[__popc(b0) + __popc(b1 & lt)] = lane + 32;
            if (lane == 0) nselb[bn] = __popc(b0) + __popc(b1);
        }
    };

    if (njs > 0) do_fill(jlist[0], 0);
    __syncthreads();

    // ---- PV static ownership: warp = 16q x 32d, lane = 1q x 16d ----
    const int pvq = (w & 3) * 16 + (lane & 15);
    const int pvd = (w >> 2) * 32 + (lane >> 4) * 16;
    float2 acc[8];
    #pragma unroll
    for (int i = 0; i < 8; i++) acc[i] = make_float2(0.0f, 0.0f);

    for (int ii = 0; ii < njs; ii++) {
        const int b = ii & 1;
        const int j = jlist[ii];
        float* ps  = psb[b];
        float* scl = sclb[b];

        // ============ Phase A: compacted score, c=4 queries/warp ============
        const int nsel = nselb[b];
        const int nw = (nsel + 3) >> 2;
        if (w < nw) {
            int qi[4]; const float* qp[4];
            #pragma unroll
            for (int u = 0; u < 4; u++) {
                qi[u] = listb[b][w * 4 + u];
                qp[u] = qs + qi[u] * DQK;
            }
            float s0[4] = {0.f, 0.f, 0.f, 0.f};
            float s1[4] = {0.f, 0.f, 0.f, 0.f};
            const float* kr = kT + 2 * lane;
            #pragma unroll 2
            for (int d = 0; d < DQK; d += 4) {
                const float2 k0 = *(const float2*)(kr + (d + 0) * KTP);
                const float2 k1 = *(const float2*)(kr + (d + 1) * KTP);
                const float2 k2 = *(const float2*)(kr + (d + 2) * KTP);
                const float2 k3 = *(const float2*)(kr + (d + 3) * KTP);
                #pragma unroll
                for (int u = 0; u < 4; u++) {
                    const float4 f = *(const float4*)(qp[u] + d);
                    s0[u] += f.x * k0.x; s1[u] += f.x * k0.y;
                    s0[u] += f.y * k1.x; s1[u] += f.y * k1.y;
                    s0[u] += f.z * k2.x; s1[u] += f.z * k2.y;
                    s0[u] += f.w * k3.x; s1[u] += f.w * k3.y;
                }
            }
            const int sg = j * 64 + 2 * lane;
            #pragma unroll
            for (int u = 0; u < 4; u++) {
                const int tq = t0 + qi[u] - seq0;
                float a0 = (sg     <= tq) ? s0[u] * SMSCALE : -1e30f;
                float a1 = (sg + 1 <= tq) ? s1[u] * SMSCALE : -1e30f;
                float mx = fmaxf(a0, a1);
                #pragma unroll
                for (int o = 16; o; o >>= 1)
                    mx = fmaxf(mx, __shfl_xor_sync(0xffffffffu, mx, o));
                const float mo = ms[qi[u]];
                const float mn = fmaxf(mo, mx);
                const float p0 = __expf(a0 - mn), p1 = __expf(a1 - mn);
                float r = p0 + p1;
                #pragma unroll
                for (int o = 16; o; o >>= 1)
                    r += __shfl_xor_sync(0xffffffffu, r, o);
                ps[(2 * lane)     * PPAD + qi[u]] = p0;
                ps[(2 * lane + 1) * PPAD + qi[u]] = p1;
                if (lane == 0) {
                    float sc = __expf(mo - mn);
                    scl[qi[u]] = sc;
                    ls[qi[u]] = ls[qi[u]] * sc + r;
                    ms[qi[u]] = mn;
                }
            }
        }
        __syncthreads();

        // ============ Phase B: fill(j+1) overlapped with PV(j) ============
        if (ii + 1 < njs) do_fill(jlist[ii + 1], b ^ 1);
        {
            const float sc = scl[pvq];
            const float2 scp = make_float2(sc, sc);
            #pragma unroll
            for (int i = 0; i < 8; i++) fmul2(acc[i], scp);
            const float* vbase = vsb[b] + pvd;
            #pragma unroll 4
            for (int s = 0; s < 64; s++) {
                const float p = ps[s * PPAD + pvq];
                const float2 pp = make_float2(p, p);
                const float4* vp = (const float4*)(vbase + s * DV);
                const float4 b0 = vp[0], b1 = vp[1], b2 = vp[2], b3 = vp[3];
                ffma2(acc[0], make_float2(b0.x, b0.y), pp);
                ffma2(acc[1], make_float2(b0.z, b0.w), pp);
                ffma2(acc[2], make_float2(b1.x, b1.y), pp);
                ffma2(acc[3], make_float2(b1.z, b1.w), pp);
                ffma2(acc[4], make_float2(b2.x, b2.y), pp);
                ffma2(acc[5], make_float2(b2.z, b2.w), pp);
                ffma2(acc[6], make_float2(b3.x, b3.y), pp);
                ffma2(acc[7], make_float2(b3.z, b3.w), pp);
            }
        }
        __syncthreads();
    }

    // ---- finalize ----
    const float invl = 1.0f / ls[pvq];
    float* op = out + (size_t)(t0 + pvq) * (HQ * DV) + (size_t)h * DV + pvd;
    float4 o0, o1, o2, o3;
    o0.x = acc[0].x * invl; o0.y = acc[0].y * invl; o0.z = acc[1].x * invl; o0.w = acc[1].y * invl;
    o1.x = acc[2].x * invl; o1.y = acc[2].y * invl; o1.z = acc[3].x * invl; o1.w = acc[3].y * invl;
    o2.x = acc[4].x * invl; o2.y = acc[4].y * invl; o2.z = acc[5].x * invl; o2.w = acc[5].y * invl;
    o3.x = acc[6].x * invl; o3.y = acc[6].y * invl; o3.z = acc[7].x * invl; o3.w = acc[7].y * invl;
    *(float4*)(op)      = o0;
    *(float4*)(op + 4)  = o1;
    *(float4*)(op + 8)  = o2;
    *(float4*)(op + 12) = o3;
}

extern "C" void kernel_launch(void* const* d_in, const int* in_sizes, int n_in,
                              void* d_out, int out_size) {
    const float* q   = (const float*)d_in[0];
    const float* k   = (const float*)d_in[1];
    const float* v   = (const float*)d_in[2];
    const int*   idx = (const int*)d_in[3];
    const int*   slp = (n_in >= 6) ? (const int*)d_in[5] : nullptr;
    float* out = (float*)d_out;

    const int T = in_sizes[0] / (HQ * DQK);

    static bool attr_set = false;
    if (!attr_set) {
        cudaFuncSetAttribute(selattn_kernel,
                             cudaFuncAttributeMaxDynamicSharedMemorySize, SMEM_BYTES);
        attr_set = true;
    }

    dim3 grid(T / QT, HQ);
    selattn_kernel<<<grid, THREADS, SMEM_BYTES>>>(q, k, v, idx, slp, out);
}

// round 7
// speedup vs baseline: 1.6302x; 1.4415x over previous
#include <cuda_runtime.h>
#include <math.h>
#include <string.h>

#define HQ    16
#define GRP   4
#define TOPK  16
#define DQK   192
#define DV    128
#define QT    64
#define THREADS 512
#define KTP   66     // EVEN: float2 kT loads stay 8B-aligned
#define PPAD  68     // multiple of 4: float4 p-loads in PV stay 16B-aligned
#define NBITS 32
#define SMSCALE 0.07216878364870322f

// smem floats:
//  qs   [65][192]   = 12480 (row 64 = dummy query)
//  kT   2x[192][66] = 25344
//  vs   [64][128]   =  8192
//  ps   2x[64][68]  =  8704
//  ms/ls [65], scl 2x[65], selm[64]u, list 2x[64], nsel[2], jlist[33], njs
#define SMEM_FLOATS (12480 + 25344 + 8192 + 8704 + 65 + 65 + 130 + 64 + 128 + 2 + 33 + 1)
#define SMEM_BYTES  (SMEM_FLOATS * 4)

__device__ __forceinline__ void ffma2(float2& d, const float2 a, const float2 b) {
    unsigned long long ua, ub;
    memcpy(&ua, &a, 8); memcpy(&ub, &b, 8);
    unsigned long long* pd = reinterpret_cast<unsigned long long*>(&d);
    asm("fma.rn.f32x2 %0, %1, %2, %0;" : "+l"(*pd) : "l"(ua), "l"(ub));
}
__device__ __forceinline__ void fmul2(float2& d, const float2 b) {
    unsigned long long ub;
    memcpy(&ub, &b, 8);
    unsigned long long* pd = reinterpret_cast<unsigned long long*>(&d);
    asm("mul.rn.f32x2 %0, %0, %1;" : "+l"(*pd) : "l"(ub));
}
__device__ __forceinline__ float2 dup2(float x) {
    float2 r;
    unsigned long long* pr = reinterpret_cast<unsigned long long*>(&r);
    asm("mov.b64 %0, {%1, %1};" : "=l"(*pr) : "f"(x));
    return r;
}

__global__ __launch_bounds__(THREADS, 1)
void selattn_kernel(const float* __restrict__ q, const float* __restrict__ k,
                    const float* __restrict__ v, const int* __restrict__ sidx,
                    const int* __restrict__ slp, float* __restrict__ out) {
    extern __shared__ float sh[];
    float* qs  = sh;                              // [65][192]
    float* kTb[2]; kTb[0] = qs + 65 * DQK; kTb[1] = kTb[0] + DQK * KTP;
    float* vs  = kTb[1] + DQK * KTP;              // [64][128]
    float* psb[2]; psb[0] = vs + 64 * DV; psb[1] = psb[0] + 64 * PPAD;
    float* ms  = psb[1] + 64 * PPAD;              // [65]
    float* ls  = ms + 65;                         // [65]
    float* sclb[2]; sclb[0] = ls + 65; sclb[1] = sclb[0] + 65;
    unsigned* selm = (unsigned*)(sclb[1] + 65);   // [64]
    int* listb[2]; listb[0] = (int*)(selm + 64); listb[1] = listb[0] + 64;
    int* nselb  = listb[1] + 64;                  // [2]
    int* jlist  = nselb + 2;                      // [33]
    int* njsp   = jlist + 33;

    const int S    = slp ? slp[0] : 2048;
    const int qt   = blockIdx.x;
    const int h    = blockIdx.y;
    const int g    = h >> 2;
    const int t0   = qt * QT;
    const int seq0 = (t0 / S) * S;
    const int tid  = threadIdx.x;
    const int lane = tid & 31;
    const int w    = tid >> 5;

    // ================= prologue =================
    for (int f = tid; f < QT * (DQK / 4); f += THREADS) {
        int qi = f / (DQK / 4), dq = f % (DQK / 4);
        ((float4*)qs)[qi * (DQK / 4) + dq] =
            ((const float4*)(q + (size_t)(t0 + qi) * HQ * DQK + (size_t)h * DQK))[dq];
    }
    if (tid < DQK) qs[QT * DQK + tid] = 0.0f;     // dummy query row
    if (tid < QT)  selm[tid] = 0u;
    if (tid < 65) { ms[tid] = -1e30f; ls[tid] = 0.0f; }
    __syncthreads();

    for (int f = tid; f < QT * TOPK; f += THREADS) {
        int qi = f >> 4, kk = f & 15;
        int b = sidx[(size_t)(t0 + qi) * (GRP * TOPK) + g * TOPK + kk] & 31;
        atomicOr(&selm[qi], 1u << b);
    }
    __syncthreads();
    if (tid < QT) {
        int tq = (t0 + tid) - seq0;
        int bt = tq >> 6;
        unsigned causal = (bt >= 31) ? 0xffffffffu : ((1u << (bt + 1)) - 1u);
        selm[tid] &= causal;
    }
    __syncthreads();
    if (tid == 0) {
        unsigned u = 0;
        #pragma unroll
        for (int i = 0; i < QT; i++) u |= selm[i];
        int n = 0;
        for (int j = 0; j < NBITS; j++)
            if ((u >> j) & 1u) jlist[n++] = j;
        *njsp = n;
    }
    __syncthreads();
    const int njs = *njsp;

    // prologue fill for block 0: kT[0], ps[0]=0, scl[0]=1, list[0]
    if (njs > 0) {
        const int j0 = jlist[0];
        const float* kblk = k + ((size_t)(seq0 + j0 * 64) * HQ + h) * DQK;
        for (int f = tid; f < 64 * DQK; f += THREADS) {
            int s = f / DQK, d = f - s * DQK;
            kTb[0][d * KTP + s] = kblk[(size_t)s * HQ * DQK + d];
        }
        for (int f = tid; f < (64 * PPAD) / 4; f += THREADS)
            ((float4*)psb[0])[f] = make_float4(0.f, 0.f, 0.f, 0.f);
        if (tid < 65) sclb[0][tid] = 1.0f;
        if (w == 0) {
            int* lb = listb[0];
            lb[lane] = 64; lb[lane + 32] = 64;
            __syncwarp();
            bool a0 = (selm[lane]      >> j0) & 1u;
            bool a1 = (selm[lane + 32] >> j0) & 1u;
            unsigned b0 = __ballot_sync(0xffffffffu, a0);
            unsigned b1 = __ballot_sync(0xffffffffu, a1);
            unsigned lt = (1u << lane) - 1u;
            if (a0) lb[__popc(b0 & lt)] = lane;
            if (a1) lb[__popc(b0) + __popc(b1 & lt)] = lane + 32;
            if (lane == 0) nselb[0] = __popc(b0) + __popc(b1);
        }
    }
    __syncthreads();

    // PV warps (w8-15): warp owns 8 queries, lane owns 4 dims for all 8
    const int qbase = (w - 8) * 8;                // valid for w>=8
    float2 acc[8][2];
    #pragma unroll
    for (int i = 0; i < 8; i++) { acc[i][0] = make_float2(0.f, 0.f); acc[i][1] = make_float2(0.f, 0.f); }

    for (int ii = 0; ii < njs; ii++) {
        const int b = ii & 1;
        const int j = jlist[ii];
        float* kT  = kTb[b];
        float* ps  = psb[b];
        float* scl = sclb[b];

        // ===== Phase A: score (w0-7, c=4, chunked) || V-fill (w8-15) =====
        if (w < 8) {
            const int nsel = nselb[b];
            const int sg = j * 64 + 2 * lane;
            for (int cb = 0; cb < nsel; cb += 32) {
                if (cb + w * 4 >= nsel) break;
                int qi[4]; const float* qp[4];
                #pragma unroll
                for (int u = 0; u < 4; u++) {
                    qi[u] = listb[b][cb + w * 4 + u];
                    qp[u] = qs + qi[u] * DQK;
                }
                float s0[4] = {0.f, 0.f, 0.f, 0.f};
                float s1[4] = {0.f, 0.f, 0.f, 0.f};
                const float* kr = kT + 2 * lane;
                #pragma unroll 2
                for (int d = 0; d < DQK; d += 4) {
                    const float2 k0 = *(const float2*)(kr + (d + 0) * KTP);
                    const float2 k1 = *(const float2*)(kr + (d + 1) * KTP);
                    const float2 k2 = *(const float2*)(kr + (d + 2) * KTP);
                    const float2 k3 = *(const float2*)(kr + (d + 3) * KTP);
                    #pragma unroll
                    for (int u = 0; u < 4; u++) {
                        const float4 f = *(const float4*)(qp[u] + d);
                        s0[u] += f.x * k0.x; s1[u] += f.x * k0.y;
                        s0[u] += f.y * k1.x; s1[u] += f.y * k1.y;
                        s0[u] += f.z * k2.x; s1[u] += f.z * k2.y;
                        s0[u] += f.w * k3.x; s1[u] += f.w * k3.y;
                    }
                }
                #pragma unroll
                for (int u = 0; u < 4; u++) {
                    const int tq = t0 + qi[u] - seq0;
                    float a0 = (sg     <= tq) ? s0[u] * SMSCALE : -1e30f;
                    float a1 = (sg + 1 <= tq) ? s1[u] * SMSCALE : -1e30f;
                    float mx = fmaxf(a0, a1);
                    #pragma unroll
                    for (int o = 16; o; o >>= 1)
                        mx = fmaxf(mx, __shfl_xor_sync(0xffffffffu, mx, o));
                    const float mo = ms[qi[u]];
                    const float mn = fmaxf(mo, mx);
                    const float p0 = __expf(a0 - mn), p1 = __expf(a1 - mn);
                    float r = p0 + p1;
                    #pragma unroll
                    for (int o = 16; o; o >>= 1)
                        r += __shfl_xor_sync(0xffffffffu, r, o);
                    ps[(2 * lane)     * PPAD + qi[u]] = p0;
                    ps[(2 * lane + 1) * PPAD + qi[u]] = p1;
                    if (lane == 0) {
                        float sc = __expf(mo - mn);
                        scl[qi[u]] = sc;
                        ls[qi[u]] = ls[qi[u]] * sc + r;
                        ms[qi[u]] = mn;
                    }
                }
            }
        } else {
            // V-fill for block j (vs read only in Phase B)
            const float* vblk = v + ((size_t)(seq0 + j * 64) * HQ + h) * DV;
            for (int f = tid - 256; f < 64 * (DV / 4); f += 256) {
                int s = f >> 5, c = f & 31;
                ((float4*)vs)[s * 32 + c] =
                    ((const float4*)vblk)[(size_t)s * HQ * (DV / 4) + c];
            }
        }
        __syncthreads();

        // ===== Phase B: kT/ps/scl/list fill for j+1 (w0-7) || PV(j) (w8-15) =====
        if (w < 8) {
            if (ii + 1 < njs) {
                const int jn = jlist[ii + 1];
                const int bn = b ^ 1;
                const float* kblk = k + ((size_t)(seq0 + jn * 64) * HQ + h) * DQK;
                float* kTn = kTb[bn];
                for (int f = tid; f < 64 * DQK; f += 256) {
                    int s = f / DQK, d = f - s * DQK;
                    kTn[d * KTP + s] = kblk[(size_t)s * HQ * DQK + d];
                }
                float4* pz = (float4*)psb[bn];
                for (int f = tid; f < (64 * PPAD) / 4; f += 256)
                    pz[f] = make_float4(0.f, 0.f, 0.f, 0.f);
                if (tid < 65) sclb[bn][tid] = 1.0f;
                if (w == 0) {
                    int* lb = listb[bn];
                    lb[lane] = 64; lb[lane + 32] = 64;
                    __syncwarp();
                    bool a0 = (selm[lane]      >> jn) & 1u;
                    bool a1 = (selm[lane + 32] >> jn) & 1u;
                    unsigned b0 = __ballot_sync(0xffffffffu, a0);
                    unsigned b1 = __ballot_sync(0xffffffffu, a1);
                    unsigned lt = (1u << lane) - 1u;
                    if (a0) lb[__popc(b0 & lt)] = lane;
                    if (a1) lb[__popc(b0) + __popc(b1 & lt)] = lane + 32;
                    if (lane == 0) nselb[bn] = __popc(b0) + __popc(b1);
                }
            }
        } else {
            // PV(j): lane owns dims [4*lane, 4*lane+4) for queries qbase..qbase+7
            float scv[8];
            #pragma unroll
            for (int i = 0; i < 8; i++) scv[i] = scl[qbase + i];
            #pragma unroll
            for (int i = 0; i < 8; i++) {
                const float2 scp = dup2(scv[i]);
                fmul2(acc[i][0], scp);
                fmul2(acc[i][1], scp);
            }
            const float* vp0 = vs + 4 * lane;
            #pragma unroll 4
            for (int s = 0; s < 64; s++) {
                const float4 vv = *(const float4*)(vp0 + s * DV);
                const float2 vlo = make_float2(vv.x, vv.y);
                const float2 vhi = make_float2(vv.z, vv.w);
                const float4 pA = *(const float4*)(ps + s * PPAD + qbase);
                const float4 pB = *(const float4*)(ps + s * PPAD + qbase + 4);
                ffma2(acc[0][0], vlo, dup2(pA.x)); ffma2(acc[0][1], vhi, dup2(pA.x));
                ffma2(acc[1][0], vlo, dup2(pA.y)); ffma2(acc[1][1], vhi, dup2(pA.y));
                ffma2(acc[2][0], vlo, dup2(pA.z)); ffma2(acc[2][1], vhi, dup2(pA.z));
                ffma2(acc[3][0], vlo, dup2(pA.w)); ffma2(acc[3][1], vhi, dup2(pA.w));
                ffma2(acc[4][0], vlo, dup2(pB.x)); ffma2(acc[4][1], vhi, dup2(pB.x));
                ffma2(acc[5][0], vlo, dup2(pB.y)); ffma2(acc[5][1], vhi, dup2(pB.y));
                ffma2(acc[6][0], vlo, dup2(pB.z)); ffma2(acc[6][1], vhi, dup2(pB.z));
                ffma2(acc[7][0], vlo, dup2(pB.w)); ffma2(acc[7][1], vhi, dup2(pB.w));
            }
        }
        __syncthreads();
    }

    // ================= finalize (PV warps) =================
    if (w >= 8) {
        #pragma unroll
        for (int i = 0; i < 8; i++) {
            const int qi = qbase + i;
            const float invl = 1.0f / ls[qi];
            float* op = out + (size_t)(t0 + qi) * (HQ * DV) + (size_t)h * DV + 4 * lane;
            float4 o;
            o.x = acc[i][0].x * invl; o.y = acc[i][0].y * invl;
            o.z = acc[i][1].x * invl; o.w = acc[i][1].y * invl;
            *(float4*)op = o;
        }
    }
}

extern "C" void kernel_launch(void* const* d_in, const int* in_sizes, int n_in,
                              void* d_out, int out_size) {
    const float* q   = (const float*)d_in[0];
    const float* k   = (const float*)d_in[1];
    const float* v   = (const float*)d_in[2];
    const int*   idx = (const int*)d_in[3];
    const int*   slp = (n_in >= 6) ? (const int*)d_in[5] : nullptr;
    float* out = (float*)d_out;

    const int T = in_sizes[0] / (HQ * DQK);

    static bool attr_set = false;
    if (!attr_set) {
        cudaFuncSetAttribute(selattn_kernel,
                             cudaFuncAttributeMaxDynamicSharedMemorySize, SMEM_BYTES);
        attr_set = true;
    }

    dim3 grid(T / QT, HQ);
    selattn_kernel<<<grid, THREADS, SMEM_BYTES>>>(q, k, v, idx, slp, out);
}

// round 8
// speedup vs baseline: 1.9395x; 1.1898x over previous
#include <cuda_runtime.h>
#include <math.h>
#include <string.h>

#define HQ    16
#define GRP   4
#define TOPK  16
#define DQK   192
#define DV    128
#define QT    64
#define THREADS 512
#define KP    196    // ks row pad: %4==0 (16B loads), lane-stride 49*16B odd -> conflict-free
#define PPAD  68     // %4==0: float4 p-loads 16B-aligned
#define NBITS 32
#define SMSCALE 0.07216878364870322f

// smem floats:
//  qs [65][192]=12480, ks 2x[64][196]=25088, vs [64][128]=8192, ps 2x[64][68]=8704,
//  ms/ls [65], scl 2x[65], selm[64], list 2x[64], nsel[2], jlist[33], njs
#define SMEM_FLOATS (12480 + 25088 + 8192 + 8704 + 65 + 65 + 130 + 64 + 128 + 2 + 33 + 1)
#define SMEM_BYTES  (SMEM_FLOATS * 4)

__device__ __forceinline__ void ffma2(float2& d, const float2 a, const float2 b) {
    unsigned long long ua, ub;
    memcpy(&ua, &a, 8); memcpy(&ub, &b, 8);
    unsigned long long* pd = reinterpret_cast<unsigned long long*>(&d);
    asm("fma.rn.f32x2 %0, %1, %2, %0;" : "+l"(*pd) : "l"(ua), "l"(ub));
}
__device__ __forceinline__ void fmul2(float2& d, const float2 b) {
    unsigned long long ub;
    memcpy(&ub, &b, 8);
    unsigned long long* pd = reinterpret_cast<unsigned long long*>(&d);
    asm("mul.rn.f32x2 %0, %0, %1;" : "+l"(*pd) : "l"(ub));
}
__device__ __forceinline__ float2 dup2(float x) {
    float2 r;
    unsigned long long* pr = reinterpret_cast<unsigned long long*>(&r);
    asm("mov.b64 %0, {%1, %1};" : "=l"(*pr) : "f"(x));
    return r;
}

__global__ __launch_bounds__(THREADS, 1)
void selattn_kernel(const float* __restrict__ q, const float* __restrict__ k,
                    const float* __restrict__ v, const int* __restrict__ sidx,
                    const int* __restrict__ slp, float* __restrict__ out) {
    extern __shared__ float sh[];
    float* qs  = sh;                              // [65][192]
    float* ksb[2]; ksb[0] = qs + 65 * DQK; ksb[1] = ksb[0] + 64 * KP;
    float* vs  = ksb[1] + 64 * KP;                // [64][128]
    float* psb[2]; psb[0] = vs + 64 * DV; psb[1] = psb[0] + 64 * PPAD;
    float* ms  = psb[1] + 64 * PPAD;              // [65]
    float* ls  = ms + 65;                         // [65]
    float* sclb[2]; sclb[0] = ls + 65; sclb[1] = sclb[0] + 65;
    unsigned* selm = (unsigned*)(sclb[1] + 65);   // [64]
    int* listb[2]; listb[0] = (int*)(selm + 64); listb[1] = listb[0] + 64;
    int* nselb  = listb[1] + 64;                  // [2]
    int* jlist  = nselb + 2;                      // [33]
    int* njsp   = jlist + 33;

    const int S    = slp ? slp[0] : 2048;
    const int qt   = blockIdx.x;
    const int h    = blockIdx.y;
    const int g    = h >> 2;
    const int t0   = qt * QT;
    const int seq0 = (t0 / S) * S;
    const int tid  = threadIdx.x;
    const int lane = tid & 31;
    const int w    = tid >> 5;

    // ================= prologue =================
    for (int f = tid; f < QT * (DQK / 4); f += THREADS) {
        int qi = f / (DQK / 4), dq = f % (DQK / 4);
        ((float4*)qs)[qi * (DQK / 4) + dq] =
            ((const float4*)(q + (size_t)(t0 + qi) * HQ * DQK + (size_t)h * DQK))[dq];
    }
    if (tid < DQK) qs[QT * DQK + tid] = 0.0f;     // dummy query row (padded list slots)
    if (tid < QT)  selm[tid] = 0u;
    if (tid < 65) { ms[tid] = -1e30f; ls[tid] = 0.0f; }
    __syncthreads();

    for (int f = tid; f < QT * TOPK; f += THREADS) {
        int qi = f >> 4, kk = f & 15;
        int b = sidx[(size_t)(t0 + qi) * (GRP * TOPK) + g * TOPK + kk] & 31;
        atomicOr(&selm[qi], 1u << b);
    }
    __syncthreads();
    if (tid < QT) {
        int tq = (t0 + tid) - seq0;
        int bt = tq >> 6;
        unsigned causal = (bt >= 31) ? 0xffffffffu : ((1u << (bt + 1)) - 1u);
        selm[tid] &= causal;
    }
    __syncthreads();
    if (tid == 0) {
        unsigned u = 0;
        #pragma unroll
        for (int i = 0; i < QT; i++) u |= selm[i];
        int n = 0;
        for (int j = 0; j < NBITS; j++)
            if ((u >> j) & 1u) jlist[n++] = j;
        *njsp = n;
    }
    __syncthreads();
    const int njs = *njsp;

    // helper: compact list for block jn into buffer bn (warp 0 of caller set)
    auto compact = [&](int jn, int bn) {
        int* lb = listb[bn];
        lb[lane] = 64; lb[lane + 32] = 64;
        __syncwarp();
        bool a0 = (selm[lane]      >> jn) & 1u;
        bool a1 = (selm[lane + 32] >> jn) & 1u;
        unsigned b0 = __ballot_sync(0xffffffffu, a0);
        unsigned b1 = __ballot_sync(0xffffffffu, a1);
        unsigned lt = (1u << lane) - 1u;
        if (a0) lb[__popc(b0 & lt)] = lane;
        if (a1) lb[__popc(b0) + __popc(b1 & lt)] = lane + 32;
        if (lane == 0) nselb[bn] = __popc(b0) + __popc(b1);
    };

    // prologue fill for block 0: ks[0] (row-major float4 copy), ps[0]=0, scl[0]=1, list[0]
    if (njs > 0) {
        const int j0 = jlist[0];
        const float* kblk = k + ((size_t)(seq0 + j0 * 64) * HQ + h) * DQK;
        for (int f = tid; f < 64 * (DQK / 4); f += THREADS) {
            int s = f / 48, dq = f % 48;
            ((float4*)(ksb[0] + s * KP))[dq] =
                ((const float4*)(kblk + (size_t)s * HQ * DQK))[dq];
        }
        for (int f = tid; f < (64 * PPAD) / 4; f += THREADS)
            ((float4*)psb[0])[f] = make_float4(0.f, 0.f, 0.f, 0.f);
        if (tid < 65) sclb[0][tid] = 1.0f;
        if (w == 0) compact(jlist[0], 0);
    }
    __syncthreads();

    // PV warps (w8-15): warp owns 8 queries, lane owns 4 dims
    const int qbase = (w - 8) * 8;
    float2 acc[8][2];
    #pragma unroll
    for (int i = 0; i < 8; i++) { acc[i][0] = make_float2(0.f, 0.f); acc[i][1] = make_float2(0.f, 0.f); }

    for (int ii = 0; ii < njs; ii++) {
        const int b = ii & 1;
        const int j = jlist[ii];
        float* ks  = ksb[b];
        float* ps  = psb[b];
        float* scl = sclb[b];

        // ===== Phase A: score (w0-7, c=4, d-paired f32x2) || V-fill (w8-15) =====
        if (w < 8) {
            const int nsel = nselb[b];
            const int sg0 = j * 64 + lane;        // kv = lane
            const int sg1 = j * 64 + 32 + lane;   // kv = lane + 32
            const float* kr0 = ks + lane * KP;
            const float* kr1 = ks + (lane + 32) * KP;
            for (int cb = 0; cb < nsel; cb += 32) {
                if (cb + w * 4 >= nsel) break;
                int qi[4]; const float* qp[4];
                #pragma unroll
                for (int u = 0; u < 4; u++) {
                    qi[u] = listb[b][cb + w * 4 + u];
                    qp[u] = qs + qi[u] * DQK;
                }
                float2 a0[4], a1[4];
                #pragma unroll
                for (int u = 0; u < 4; u++) {
                    a0[u] = make_float2(0.f, 0.f);
                    a1[u] = make_float2(0.f, 0.f);
                }
                #pragma unroll 2
                for (int d = 0; d < DQK; d += 4) {
                    const float4 kA = *(const float4*)(kr0 + d);
                    const float4 kB = *(const float4*)(kr1 + d);
                    const float2 kA0 = make_float2(kA.x, kA.y);
                    const float2 kA1 = make_float2(kA.z, kA.w);
                    const float2 kB0 = make_float2(kB.x, kB.y);
                    const float2 kB1 = make_float2(kB.z, kB.w);
                    #pragma unroll
                    for (int u = 0; u < 4; u++) {
                        const float4 qv = *(const float4*)(qp[u] + d);
                        const float2 q0 = make_float2(qv.x, qv.y);
                        const float2 q1 = make_float2(qv.z, qv.w);
                        ffma2(a0[u], q0, kA0);
                        ffma2(a0[u], q1, kA1);
                        ffma2(a1[u], q0, kB0);
                        ffma2(a1[u], q1, kB1);
                    }
                }
                #pragma unroll
                for (int u = 0; u < 4; u++) {
                    const int tq = t0 + qi[u] - seq0;
                    float v0 = a0[u].x + a0[u].y;
                    float v1 = a1[u].x + a1[u].y;
                    float e0 = (sg0 <= tq) ? v0 * SMSCALE : -1e30f;
                    float e1 = (sg1 <= tq) ? v1 * SMSCALE : -1e30f;
                    float mx = fmaxf(e0, e1);
                    #pragma unroll
                    for (int o = 16; o; o >>= 1)
                        mx = fmaxf(mx, __shfl_xor_sync(0xffffffffu, mx, o));
                    const float mo = ms[qi[u]];
                    const float mn = fmaxf(mo, mx);
                    const float p0 = __expf(e0 - mn), p1 = __expf(e1 - mn);
                    float r = p0 + p1;
                    #pragma unroll
                    for (int o = 16; o; o >>= 1)
                        r += __shfl_xor_sync(0xffffffffu, r, o);
                    ps[lane * PPAD + qi[u]]        = p0;
                    ps[(lane + 32) * PPAD + qi[u]] = p1;
                    if (lane == 0) {
                        float sc = __expf(mo - mn);
                        scl[qi[u]] = sc;
                        ls[qi[u]] = ls[qi[u]] * sc + r;
                        ms[qi[u]] = mn;
                    }
                }
            }
        } else {
            // V-fill(j): vs read only in Phase B
            const float* vblk = v + ((size_t)(seq0 + j * 64) * HQ + h) * DV;
            for (int f = tid - 256; f < 64 * (DV / 4); f += 256) {
                int s = f >> 5, c = f & 31;
                ((float4*)vs)[s * 32 + c] =
                    ((const float4*)vblk)[(size_t)s * HQ * (DV / 4) + c];
            }
        }
        __syncthreads();

        // ===== Phase B: ks/ps/scl/list fill(j+1) (w0-7) || PV(j) (w8-15) =====
        if (w < 8) {
            if (ii + 1 < njs) {
                const int jn = jlist[ii + 1];
                const int bn = b ^ 1;
                const float* kblk = k + ((size_t)(seq0 + jn * 64) * HQ + h) * DQK;
                float* ksn = ksb[bn];
                for (int f = tid; f < 64 * (DQK / 4); f += 256) {
                    int s = f / 48, dq = f % 48;
                    ((float4*)(ksn + s * KP))[dq] =
                        ((const float4*)(kblk + (size_t)s * HQ * DQK))[dq];
                }
                float4* pz = (float4*)psb[bn];
                for (int f = tid; f < (64 * PPAD) / 4; f += 256)
                    pz[f] = make_float4(0.f, 0.f, 0.f, 0.f);
                if (tid < 65) sclb[bn][tid] = 1.0f;
                if (w == 0) compact(jn, bn);
            }
        } else {
            // PV(j): lane owns dims [4*lane, 4*lane+4) for queries qbase..qbase+7
            float scv[8];
            #pragma unroll
            for (int i = 0; i < 8; i++) scv[i] = scl[qbase + i];
            #pragma unroll
            for (int i = 0; i < 8; i++) {
                const float2 scp = dup2(scv[i]);
                fmul2(acc[i][0], scp);
                fmul2(acc[i][1], scp);
            }
            const float* vp0 = vs + 4 * lane;
            #pragma unroll 4
            for (int s = 0; s < 64; s++) {
                const float4 vv = *(const float4*)(vp0 + s * DV);
                const float2 vlo = make_float2(vv.x, vv.y);
                const float2 vhi = make_float2(vv.z, vv.w);
                const float4 pA = *(const float4*)(ps + s * PPAD + qbase);
                const float4 pB = *(const float4*)(ps + s * PPAD + qbase + 4);
                ffma2(acc[0][0], vlo, dup2(pA.x)); ffma2(acc[0][1], vhi, dup2(pA.x));
                ffma2(acc[1][0], vlo, dup2(pA.y)); ffma2(acc[1][1], vhi, dup2(pA.y));
                ffma2(acc[2][0], vlo, dup2(pA.z)); ffma2(acc[2][1], vhi, dup2(pA.z));
                ffma2(acc[3][0], vlo, dup2(pA.w)); ffma2(acc[3][1], vhi, dup2(pA.w));
                ffma2(acc[4][0], vlo, dup2(pB.x)); ffma2(acc[4][1], vhi, dup2(pB.x));
                ffma2(acc[5][0], vlo, dup2(pB.y)); ffma2(acc[5][1], vhi, dup2(pB.y));
                ffma2(acc[6][0], vlo, dup2(pB.z)); ffma2(acc[6][1], vhi, dup2(pB.z));
                ffma2(acc[7][0], vlo, dup2(pB.w)); ffma2(acc[7][1], vhi, dup2(pB.w));
            }
        }
        __syncthreads();
    }

    // ================= finalize (PV warps) =================
    if (w >= 8) {
        #pragma unroll
        for (int i = 0; i < 8; i++) {
            const int qi = qbase + i;
            const float invl = 1.0f / ls[qi];
            float* op = out + (size_t)(t0 + qi) * (HQ * DV) + (size_t)h * DV + 4 * lane;
            float4 o;
            o.x = acc[i][0].x * invl; o.y = acc[i][0].y * invl;
            o.z = acc[i][1].x * invl; o.w = acc[i][1].y * invl;
            *(float4*)op = o;
        }
    }
}

extern "C" void kernel_launch(void* const* d_in, const int* in_sizes, int n_in,
                              void* d_out, int out_size) {
    const float* q   = (const float*)d_in[0];
    const float* k   = (const float*)d_in[1];
    const float* v   = (const float*)d_in[2];
    const int*   idx = (const int*)d_in[3];
    const int*   slp = (n_in >= 6) ? (const int*)d_in[5] : nullptr;
    float* out = (float*)d_out;

    const int T = in_sizes[0] / (HQ * DQK);

    static bool attr_set = false;
    if (!attr_set) {
        cudaFuncSetAttribute(selattn_kernel,
                             cudaFuncAttributeMaxDynamicSharedMemorySize, SMEM_BYTES);
        attr_set = true;
    }

    dim3 grid(T / QT, HQ);
    selattn_kernel<<<grid, THREADS, SMEM_BYTES>>>(q, k, v, idx, slp, out);
}

// round 9
// speedup vs baseline: 2.0310x; 1.0472x over previous
#include <cuda_runtime.h>
#include <math.h>
#include <string.h>

#define HQ    16
#define GRP   4
#define TOPK  16
#define DQK   192
#define DV    128
#define QT    64
#define THREADS 512
#define KP    196    // ks row pad (floats): 16B-aligned, quarter-warp conflict-free
#define PPAD  68     // ps row pad: %4==0 for float4 reads
#define NBITS 32
#define SMSCALE 0.07216878364870322f

// named barriers
#define FULL0  1
#define EMPTY0 3
#define SBAR   5
#define PBAR   6
#define BAR_SYNC(id, cnt)   asm volatile("bar.sync %0, %1;"   :: "r"(id), "r"(cnt) : "memory")
#define BAR_ARRIVE(id, cnt) asm volatile("bar.arrive %0, %1;" :: "r"(id), "r"(cnt) : "memory")
#define MEMBAR_CTA()        asm volatile("membar.cta;" ::: "memory")

// smem floats: qs 12480 + ks 12544 + vs 8192 + ps 2x4352 + ms/ls 130 + scl 130
//              + selm 64 + list 128 + nsel 2 + jlist 33 + njs 1  = 42408 (~166 KB)
#define SMEM_FLOATS (12480 + 12544 + 8192 + 8704 + 130 + 130 + 64 + 128 + 2 + 33 + 1)
#define SMEM_BYTES  (SMEM_FLOATS * 4)

__device__ __forceinline__ void ffma2(float2& d, const float2 a, const float2 b) {
    unsigned long long ua, ub;
    memcpy(&ua, &a, 8); memcpy(&ub, &b, 8);
    unsigned long long* pd = reinterpret_cast<unsigned long long*>(&d);
    asm("fma.rn.f32x2 %0, %1, %2, %0;" : "+l"(*pd) : "l"(ua), "l"(ub));
}
__device__ __forceinline__ void fmul2(float2& d, const float2 b) {
    unsigned long long ub;
    memcpy(&ub, &b, 8);
    unsigned long long* pd = reinterpret_cast<unsigned long long*>(&d);
    asm("mul.rn.f32x2 %0, %0, %1;" : "+l"(*pd) : "l"(ub));
}
__device__ __forceinline__ float2 dup2(float x) {
    float2 r;
    unsigned long long* pr = reinterpret_cast<unsigned long long*>(&r);
    asm("mov.b64 %0, {%1, %1};" : "=l"(*pr) : "f"(x));
    return r;
}

__global__ __launch_bounds__(THREADS, 1)
void selattn_kernel(const float* __restrict__ q, const float* __restrict__ k,
                    const float* __restrict__ v, const int* __restrict__ sidx,
                    const int* __restrict__ slp, float* __restrict__ out) {
    extern __shared__ float sh[];
    float* qs  = sh;                               // [65][192]
    float* ks  = qs + 65 * DQK;                    // [64][196] single buffer
    float* vs  = ks + 64 * KP;                     // [64][128] single buffer
    float* psb[2]; psb[0] = vs + 64 * DV; psb[1] = psb[0] + 64 * PPAD;
    float* ms  = psb[1] + 64 * PPAD;               // [65]
    float* ls  = ms + 65;                          // [65]
    float* sclb[2]; sclb[0] = ls + 65; sclb[1] = sclb[0] + 65;
    unsigned* selm = (unsigned*)(sclb[1] + 65);    // [64]
    int* listb[2]; listb[0] = (int*)(selm + 64); listb[1] = listb[0] + 64;
    int* nselb  = listb[1] + 64;                   // [2]
    int* jlist  = nselb + 2;                       // [33]
    int* njsp   = jlist + 33;

    const int S    = slp ? slp[0] : 2048;
    const int qt   = blockIdx.x;
    const int h    = blockIdx.y;
    const int g    = h >> 2;
    const int t0   = qt * QT;
    const int seq0 = (t0 / S) * S;
    const int tid  = threadIdx.x;
    const int lane = tid & 31;
    const int w    = tid >> 5;

    // ================= prologue (all 512 threads) =================
    for (int f = tid; f < QT * (DQK / 4); f += THREADS) {
        int qi = f / (DQK / 4), dq = f % (DQK / 4);
        ((float4*)qs)[qi * (DQK / 4) + dq] =
            ((const float4*)(q + (size_t)(t0 + qi) * HQ * DQK + (size_t)h * DQK))[dq];
    }
    if (tid < DQK) qs[QT * DQK + tid] = 0.0f;      // dummy query row
    if (tid < QT)  selm[tid] = 0u;
    if (tid < 65) { ms[tid] = -1e30f; ls[tid] = 0.0f;
                    sclb[0][tid] = 1.0f; sclb[1][tid] = 1.0f; }
    __syncthreads();

    for (int f = tid; f < QT * TOPK; f += THREADS) {
        int qi = f >> 4, kk = f & 15;
        int b = sidx[(size_t)(t0 + qi) * (GRP * TOPK) + g * TOPK + kk] & 31;
        atomicOr(&selm[qi], 1u << b);
    }
    __syncthreads();
    if (tid < QT) {
        int tq = (t0 + tid) - seq0;
        int bt = tq >> 6;
        unsigned causal = (bt >= 31) ? 0xffffffffu : ((1u << (bt + 1)) - 1u);
        selm[tid] &= causal;
    }
    __syncthreads();
    if (tid == 0) {
        unsigned u = 0;
        #pragma unroll
        for (int i = 0; i < QT; i++) u |= selm[i];
        int n = 0;
        for (int j = 0; j < NBITS; j++)
            if ((u >> j) & 1u) jlist[n++] = j;
        *njsp = n;
    }
    // zero both ps buffers
    for (int f = tid; f < (2 * 64 * PPAD) / 4; f += THREADS)
        ((float4*)psb[0])[f] = make_float4(0.f, 0.f, 0.f, 0.f);
    __syncthreads();
    const int njs = *njsp;

    auto compact = [&](int jn, int bn) {     // caller: single warp
        int* lb = listb[bn];
        lb[lane] = 64; lb[lane + 32] = 64;
        __syncwarp();
        bool a0 = (selm[lane]      >> jn) & 1u;
        bool a1 = (selm[lane + 32] >> jn) & 1u;
        unsigned b0 = __ballot_sync(0xffffffffu, a0);
        unsigned b1 = __ballot_sync(0xffffffffu, a1);
        unsigned lt = (1u << lane) - 1u;
        if (a0) lb[__popc(b0 & lt)] = lane;
        if (a1) lb[__popc(b0) + __popc(b1 & lt)] = lane + 32;
        if (lane == 0) nselb[bn] = __popc(b0) + __popc(b1);
    };

    // prologue fills for block 0 (all 512 threads)
    {
        const int j0 = jlist[0];
        const float* kblk = k + ((size_t)(seq0 + j0 * 64) * HQ + h) * DQK;
        for (int f = tid; f < 64 * (DQK / 4); f += THREADS) {
            int s = f / 48, dq = f % 48;
            ((float4*)(ks + s * KP))[dq] =
                ((const float4*)(kblk + (size_t)s * HQ * DQK))[dq];
        }
        const float* vblk = v + ((size_t)(seq0 + j0 * 64) * HQ + h) * DV;
        for (int f = tid; f < 64 * (DV / 4); f += THREADS) {
            int s = f >> 5, c = f & 31;
            ((float4*)vs)[s * 32 + c] =
                ((const float4*)vblk)[(size_t)s * HQ * (DV / 4) + c];
        }
        if (w == 0) compact(j0, 0);
    }
    __syncthreads();

    if (w < 8) {
        // ===================== SCORE GROUP (warps 0-7) =====================
        const int st = tid;                        // 0..255
        for (int ii = 0; ii < njs; ii++) {
            const int b = ii & 1;
            const int j = jlist[ii];
            BAR_SYNC(EMPTY0 + b, 512);             // ps[b]/scl[b] free, list[b] ready
            float* ps  = psb[b];
            float* scl = sclb[b];
            const int nsel = nselb[b];
            if (w * 8 < nsel) {
                int qi[8]; const float* qp[8];
                #pragma unroll
                for (int u = 0; u < 8; u++) {
                    qi[u] = listb[b][w * 8 + u];
                    qp[u] = qs + qi[u] * DQK;
                }
                float2 a0[8], a1[8];
                #pragma unroll
                for (int u = 0; u < 8; u++) {
                    a0[u] = make_float2(0.f, 0.f);
                    a1[u] = make_float2(0.f, 0.f);
                }
                const float* kr0 = ks + lane * KP;
                const float* kr1 = ks + (lane + 32) * KP;
                #pragma unroll 2
                for (int d = 0; d < DQK; d += 4) {
                    const float4 kA = *(const float4*)(kr0 + d);
                    const float4 kB = *(const float4*)(kr1 + d);
                    const float2 kA0 = make_float2(kA.x, kA.y);
                    const float2 kA1 = make_float2(kA.z, kA.w);
                    const float2 kB0 = make_float2(kB.x, kB.y);
                    const float2 kB1 = make_float2(kB.z, kB.w);
                    #pragma unroll
                    for (int u = 0; u < 8; u++) {
                        const float4 qv = *(const float4*)(qp[u] + d);
                        const float2 q0 = make_float2(qv.x, qv.y);
                        const float2 q1 = make_float2(qv.z, qv.w);
                        ffma2(a0[u], q0, kA0);
                        ffma2(a0[u], q1, kA1);
                        ffma2(a1[u], q0, kB0);
                        ffma2(a1[u], q1, kB1);
                    }
                }
                const int sg0 = j * 64 + lane;
                const int sg1 = j * 64 + 32 + lane;
                #pragma unroll
                for (int u = 0; u < 8; u++) {
                    const int tq = t0 + qi[u] - seq0;
                    float v0 = a0[u].x + a0[u].y;
                    float v1 = a1[u].x + a1[u].y;
                    float e0 = (sg0 <= tq) ? v0 * SMSCALE : -1e30f;
                    float e1 = (sg1 <= tq) ? v1 * SMSCALE : -1e30f;
                    float mx = fmaxf(e0, e1);
                    #pragma unroll
                    for (int o = 16; o; o >>= 1)
                        mx = fmaxf(mx, __shfl_xor_sync(0xffffffffu, mx, o));
                    const float mo = ms[qi[u]];
                    const float mn = fmaxf(mo, mx);
                    const float p0 = __expf(e0 - mn), p1 = __expf(e1 - mn);
                    float r = p0 + p1;
                    #pragma unroll
                    for (int o = 16; o; o >>= 1)
                        r += __shfl_xor_sync(0xffffffffu, r, o);
                    ps[lane * PPAD + qi[u]]        = p0;
                    ps[(lane + 32) * PPAD + qi[u]] = p1;
                    if (lane == 0) {
                        float sc = __expf(mo - mn);
                        scl[qi[u]] = sc;
                        ls[qi[u]] = ls[qi[u]] * sc + r;
                        ms[qi[u]] = mn;
                    }
                }
            }
            MEMBAR_CTA();
            BAR_ARRIVE(FULL0 + b, 512);            // ps[b]/scl[b] ready for PV
            BAR_SYNC(SBAR, 256);                   // all score warps done reading ks
            if (ii + 1 < njs) {
                const int jn = jlist[ii + 1];
                const float* kblk = k + ((size_t)(seq0 + jn * 64) * HQ + h) * DQK;
                for (int f = st; f < 64 * (DQK / 4); f += 256) {
                    int s = f / 48, dq = f % 48;
                    ((float4*)(ks + s * KP))[dq] =
                        ((const float4*)(kblk + (size_t)s * HQ * DQK))[dq];
                }
                if (w == 0) compact(jn, b ^ 1);
            }
        }
        // consume leftover EMPTY arrivals (balance barrier state)
        BAR_SYNC(EMPTY0 + (njs & 1), 512);
        BAR_SYNC(EMPTY0 + ((njs + 1) & 1), 512);
    } else {
        // ===================== PV GROUP (warps 8-15) =====================
        const int pt = tid - 256;                  // 0..255
        const int qbase = (w - 8) * 8;
        float2 acc[8][2];
        #pragma unroll
        for (int i = 0; i < 8; i++) { acc[i][0] = make_float2(0.f, 0.f); acc[i][1] = make_float2(0.f, 0.f); }

        BAR_ARRIVE(EMPTY0, 512);                   // pre-arm both EMPTY barriers
        BAR_ARRIVE(EMPTY0 + 1, 512);

        for (int ii = 0; ii < njs; ii++) {
            const int b = ii & 1;
            BAR_SYNC(FULL0 + b, 512);              // ps[b]/scl[b] ready; vs fill done
            float* ps  = psb[b];
            float* scl = sclb[b];
            {
                float scv[8];
                #pragma unroll
                for (int i = 0; i < 8; i++) scv[i] = scl[qbase + i];
                #pragma unroll
                for (int i = 0; i < 8; i++) {
                    const float2 scp = dup2(scv[i]);
                    fmul2(acc[i][0], scp);
                    fmul2(acc[i][1], scp);
                }
                const float* vp0 = vs + 4 * lane;
                #pragma unroll 4
                for (int s = 0; s < 64; s++) {
                    const float4 vv = *(const float4*)(vp0 + s * DV);
                    const float2 vlo = make_float2(vv.x, vv.y);
                    const float2 vhi = make_float2(vv.z, vv.w);
                    const float4 pA = *(const float4*)(ps + s * PPAD + qbase);
                    const float4 pB = *(const float4*)(ps + s * PPAD + qbase + 4);
                    ffma2(acc[0][0], vlo, dup2(pA.x)); ffma2(acc[0][1], vhi, dup2(pA.x));
                    ffma2(acc[1][0], vlo, dup2(pA.y)); ffma2(acc[1][1], vhi, dup2(pA.y));
                    ffma2(acc[2][0], vlo, dup2(pA.z)); ffma2(acc[2][1], vhi, dup2(pA.z));
                    ffma2(acc[3][0], vlo, dup2(pA.w)); ffma2(acc[3][1], vhi, dup2(pA.w));
                    ffma2(acc[4][0], vlo, dup2(pB.x)); ffma2(acc[4][1], vhi, dup2(pB.x));
                    ffma2(acc[5][0], vlo, dup2(pB.y)); ffma2(acc[5][1], vhi, dup2(pB.y));
                    ffma2(acc[6][0], vlo, dup2(pB.z)); ffma2(acc[6][1], vhi, dup2(pB.z));
                    ffma2(acc[7][0], vlo, dup2(pB.w)); ffma2(acc[7][1], vhi, dup2(pB.w));
                }
            }
            BAR_SYNC(PBAR, 256);                   // all PV warps done reading ps[b]/vs
            // recycle ps[b] (zero) and scl[b] (=1) before handing back
            for (int f = pt; f < (64 * PPAD) / 4; f += 256)
                ((float4*)ps)[f] = make_float4(0.f, 0.f, 0.f, 0.f);
            if (pt < 65) scl[pt] = 1.0f;
            MEMBAR_CTA();
            BAR_ARRIVE(EMPTY0 + b, 512);
            if (ii + 1 < njs) {
                const int jn = jlist[ii + 1];
                const float* vblk = v + ((size_t)(seq0 + jn * 64) * HQ + h) * DV;
                for (int f = pt; f < 64 * (DV / 4); f += 256) {
                    int s = f >> 5, c = f & 31;
                    ((float4*)vs)[s * 32 + c] =
                        ((const float4*)vblk)[(size_t)s * HQ * (DV / 4) + c];
                }
            }
        }

        // stash accumulators via registers till final sync (ls needs score group done)
        __syncthreads();
        #pragma unroll
        for (int i = 0; i < 8; i++) {
            const int qi = qbase + i;
            const float invl = 1.0f / ls[qi];
            float* op = out + (size_t)(t0 + qi) * (HQ * DV) + (size_t)h * DV + 4 * lane;
            float4 o;
            o.x = acc[i][0].x * invl; o.y = acc[i][0].y * invl;
            o.z = acc[i][1].x * invl; o.w = acc[i][1].y * invl;
            *(float4*)op = o;
        }
        return;
    }
    __syncthreads();   // score group joins PV group's final sync
}

extern "C" void kernel_launch(void* const* d_in, const int* in_sizes, int n_in,
                              void* d_out, int out_size) {
    const float* q   = (const float*)d_in[0];
    const float* k   = (const float*)d_in[1];
    const float* v   = (const float*)d_in[2];
    const int*   idx = (const int*)d_in[3];
    const int*   slp = (n_in >= 6) ? (const int*)d_in[5] : nullptr;
    float* out = (float*)d_out;

    const int T = in_sizes[0] / (HQ * DQK);

    static bool attr_set = false;
    if (!attr_set) {
        cudaFuncSetAttribute(selattn_kernel,
                             cudaFuncAttributeMaxDynamicSharedMemorySize, SMEM_BYTES);
        attr_set = true;
    }

    dim3 grid(T / QT, HQ);
    selattn_kernel<<<grid, THREADS, SMEM_BYTES>>>(q, k, v, idx, slp, out);
}

// round 10
// speedup vs baseline: 2.1450x; 1.0561x over previous
#include <cuda_runtime.h>
#include <math.h>
#include <string.h>

#define HQ    16
#define GRP   4
#define TOPK  16
#define DQK   192
#define DV    128
#define QT    64
#define THREADS 512
#define KP    196
#define PPAD  68
#define NBITS 32
#define SMSCALE 0.07216878364870322f

#define FULL0  1
#define EMPTY0 3
#define SBAR   5
#define PBAR   6
#define BAR_SYNC(id, cnt)   asm volatile("bar.sync %0, %1;"   :: "r"(id), "r"(cnt) : "memory")
#define BAR_ARRIVE(id, cnt) asm volatile("bar.arrive %0, %1;" :: "r"(id), "r"(cnt) : "memory")
#define MEMBAR_CTA()        asm volatile("membar.cta;" ::: "memory")

// qs 12480 + ks 12544 + vs 8192 + ps 2x4352 + ms/ls 132 + scl 132 + selm 64
// + list 128 + nsel 2 + jlist 33 + njs 1
#define SMEM_FLOATS (12480 + 12544 + 8192 + 8704 + 132 + 132 + 64 + 128 + 2 + 33 + 1)
#define SMEM_BYTES  (SMEM_FLOATS * 4)

__device__ __forceinline__ void ffma2(float2& d, const float2 a, const float2 b) {
    unsigned long long ua, ub;
    memcpy(&ua, &a, 8); memcpy(&ub, &b, 8);
    unsigned long long* pd = reinterpret_cast<unsigned long long*>(&d);
    asm("fma.rn.f32x2 %0, %1, %2, %0;" : "+l"(*pd) : "l"(ua), "l"(ub));
}
__device__ __forceinline__ void fmul2(float2& d, const float2 b) {
    unsigned long long ub;
    memcpy(&ub, &b, 8);
    unsigned long long* pd = reinterpret_cast<unsigned long long*>(&d);
    asm("mul.rn.f32x2 %0, %0, %1;" : "+l"(*pd) : "l"(ub));
}
__device__ __forceinline__ float2 dup2(float x) {
    float2 r;
    unsigned long long* pr = reinterpret_cast<unsigned long long*>(&r);
    asm("mov.b64 %0, {%1, %1};" : "=l"(*pr) : "f"(x));
    return r;
}

__global__ __launch_bounds__(THREADS, 1)
void selattn_kernel(const float* __restrict__ q, const float* __restrict__ k,
                    const float* __restrict__ v, const int* __restrict__ sidx,
                    const int* __restrict__ slp, float* __restrict__ out) {
    extern __shared__ float sh[];
    float* qs  = sh;                               // [65][192]
    float* ks  = qs + 65 * DQK;                    // [64][196]
    float* vs  = ks + 64 * KP;                     // [64][128]
    float* psb[2]; psb[0] = vs + 64 * DV; psb[1] = psb[0] + 64 * PPAD;
    float* ms  = psb[1] + 64 * PPAD;               // [66] (even base)
    float* ls  = ms + 66;                          // [66]
    float* sclb[2]; sclb[0] = ls + 66; sclb[1] = sclb[0] + 66;   // even bases
    unsigned* selm = (unsigned*)(sclb[1] + 66);    // [64]
    int* listb[2]; listb[0] = (int*)(selm + 64); listb[1] = listb[0] + 64;
    int* nselb  = listb[1] + 64;                   // [2]
    int* jlist  = nselb + 2;                       // [33]
    int* njsp   = jlist + 33;

    const int S    = slp ? slp[0] : 2048;
    const int qt   = blockIdx.x;
    const int h    = blockIdx.y;
    const int g    = h >> 2;
    const int t0   = qt * QT;
    const int seq0 = (t0 / S) * S;
    const int tid  = threadIdx.x;
    const int lane = tid & 31;
    const int w    = tid >> 5;

    // ================= prologue =================
    for (int f = tid; f < QT * (DQK / 4); f += THREADS) {
        int qi = f / (DQK / 4), dq = f % (DQK / 4);
        ((float4*)qs)[qi * (DQK / 4) + dq] =
            ((const float4*)(q + (size_t)(t0 + qi) * HQ * DQK + (size_t)h * DQK))[dq];
    }
    if (tid < DQK) qs[QT * DQK + tid] = 0.0f;      // dummy query row
    if (tid < QT)  selm[tid] = 0u;
    if (tid < 66) { ms[tid] = -1e30f; ls[tid] = 0.0f;
                    sclb[0][tid] = 1.0f; sclb[1][tid] = 1.0f; }
    __syncthreads();

    for (int f = tid; f < QT * TOPK; f += THREADS) {
        int qi = f >> 4, kk = f & 15;
        int b = sidx[(size_t)(t0 + qi) * (GRP * TOPK) + g * TOPK + kk] & 31;
        atomicOr(&selm[qi], 1u << b);
    }
    __syncthreads();
    if (tid < QT) {
        int tq = (t0 + tid) - seq0;
        int bt = tq >> 6;
        unsigned causal = (bt >= 31) ? 0xffffffffu : ((1u << (bt + 1)) - 1u);
        selm[tid] &= causal;
    }
    __syncthreads();
    if (tid == 0) {
        unsigned u = 0;
        #pragma unroll
        for (int i = 0; i < QT; i++) u |= selm[i];
        int n = 0;
        for (int j = 0; j < NBITS; j++)
            if ((u >> j) & 1u) jlist[n++] = j;
        *njsp = n;
    }
    for (int f = tid; f < (2 * 64 * PPAD) / 4; f += THREADS)
        ((float4*)psb[0])[f] = make_float4(0.f, 0.f, 0.f, 0.f);
    __syncthreads();
    const int njs = *njsp;

    auto compact = [&](int jn, int bn) {           // single warp
        int* lb = listb[bn];
        lb[lane] = 64; lb[lane + 32] = 64;
        __syncwarp();
        bool a0 = (selm[lane]      >> jn) & 1u;
        bool a1 = (selm[lane + 32] >> jn) & 1u;
        unsigned b0 = __ballot_sync(0xffffffffu, a0);
        unsigned b1 = __ballot_sync(0xffffffffu, a1);
        unsigned lt = (1u << lane) - 1u;
        if (a0) lb[__popc(b0 & lt)] = lane;
        if (a1) lb[__popc(b0) + __popc(b1 & lt)] = lane + 32;
        if (lane == 0) nselb[bn] = __popc(b0) + __popc(b1);
    };

    {   // prologue fills for block 0
        const int j0 = jlist[0];
        const float* kblk = k + ((size_t)(seq0 + j0 * 64) * HQ + h) * DQK;
        for (int f = tid; f < 64 * (DQK / 4); f += THREADS) {
            int s = f / 48, dq = f % 48;
            ((float4*)(ks + s * KP))[dq] =
                ((const float4*)(kblk + (size_t)s * HQ * DQK))[dq];
        }
        const float* vblk = v + ((size_t)(seq0 + j0 * 64) * HQ + h) * DV;
        for (int f = tid; f < 64 * (DV / 4); f += THREADS) {
            int s = f >> 5, c = f & 31;
            ((float4*)vs)[s * 32 + c] =
                ((const float4*)vblk)[(size_t)s * HQ * (DV / 4) + c];
        }
        if (w == 0) compact(j0, 0);
    }
    __syncthreads();

    if (w < 8) {
        // ===================== SCORE GROUP (warps 0-7), c=4 two-chunk =====================
        const int st = tid;
        for (int ii = 0; ii < njs; ii++) {
            const int b = ii & 1;
            const int j = jlist[ii];
            BAR_SYNC(EMPTY0 + b, 512);
            float* ps  = psb[b];
            float* scl = sclb[b];
            const int nsel = nselb[b];
            const int sg0 = j * 64 + lane;
            const int sg1 = j * 64 + 32 + lane;
            const float* kr0 = ks + lane * KP;
            const float* kr1 = ks + (lane + 32) * KP;
            for (int cb = 0; cb < nsel; cb += 32) {
                if (cb + w * 4 >= nsel) break;
                int qi[4]; const float* qp[4];
                #pragma unroll
                for (int u = 0; u < 4; u++) {
                    qi[u] = listb[b][cb + w * 4 + u];
                    qp[u] = qs + qi[u] * DQK;
                }
                float2 a0[4], a1[4];
                #pragma unroll
                for (int u = 0; u < 4; u++) {
                    a0[u] = make_float2(0.f, 0.f);
                    a1[u] = make_float2(0.f, 0.f);
                }
                #pragma unroll 2
                for (int d = 0; d < DQK; d += 4) {
                    const float4 kA = *(const float4*)(kr0 + d);
                    const float4 kB = *(const float4*)(kr1 + d);
                    const float2 kA0 = make_float2(kA.x, kA.y);
                    const float2 kA1 = make_float2(kA.z, kA.w);
                    const float2 kB0 = make_float2(kB.x, kB.y);
                    const float2 kB1 = make_float2(kB.z, kB.w);
                    #pragma unroll
                    for (int u = 0; u < 4; u++) {
                        const float4 qv = *(const float4*)(qp[u] + d);
                        const float2 q0 = make_float2(qv.x, qv.y);
                        const float2 q1 = make_float2(qv.z, qv.w);
                        ffma2(a0[u], q0, kA0);
                        ffma2(a0[u], q1, kA1);
                        ffma2(a1[u], q0, kB0);
                        ffma2(a1[u], q1, kB1);
                    }
                }
                #pragma unroll
                for (int u = 0; u < 4; u++) {
                    const int tq = t0 + qi[u] - seq0;
                    float v0 = a0[u].x + a0[u].y;
                    float v1 = a1[u].x + a1[u].y;
                    float e0 = (sg0 <= tq) ? v0 * SMSCALE : -1e30f;
                    float e1 = (sg1 <= tq) ? v1 * SMSCALE : -1e30f;
                    float mx = fmaxf(e0, e1);
                    #pragma unroll
                    for (int o = 16; o; o >>= 1)
                        mx = fmaxf(mx, __shfl_xor_sync(0xffffffffu, mx, o));
                    const float mo = ms[qi[u]];
                    const float mn = fmaxf(mo, mx);
                    const float p0 = __expf(e0 - mn), p1 = __expf(e1 - mn);
                    float r = p0 + p1;
                    #pragma unroll
                    for (int o = 16; o; o >>= 1)
                        r += __shfl_xor_sync(0xffffffffu, r, o);
                    ps[lane * PPAD + qi[u]]        = p0;
                    ps[(lane + 32) * PPAD + qi[u]] = p1;
                    if (lane == 0) {
                        float sc = __expf(mo - mn);
                        scl[qi[u]] = sc;
                        ls[qi[u]] = ls[qi[u]] * sc + r;
                        ms[qi[u]] = mn;
                    }
                }
            }
            MEMBAR_CTA();
            BAR_ARRIVE(FULL0 + b, 512);
            BAR_SYNC(SBAR, 256);
            if (ii + 1 < njs) {
                const int jn = jlist[ii + 1];
                const float* kblk = k + ((size_t)(seq0 + jn * 64) * HQ + h) * DQK;
                for (int f = st; f < 64 * (DQK / 4); f += 256) {
                    int s = f / 48, dq = f % 48;
                    ((float4*)(ks + s * KP))[dq] =
                        ((const float4*)(kblk + (size_t)s * HQ * DQK))[dq];
                }
                if (w == 0) compact(jn, b ^ 1);
            }
        }
        BAR_SYNC(EMPTY0 + (njs & 1), 512);
        BAR_SYNC(EMPTY0 + ((njs + 1) & 1), 512);
    } else {
        // ===================== PV GROUP (warps 8-15), query-paired =====================
        const int pt = tid - 256;
        const int qbase = (w - 8) * 8;
        // acc[pi*4+d] = float2 over query pair (qbase+2pi, qbase+2pi+1), dim 4*lane+d
        float2 acc[16];
        #pragma unroll
        for (int i = 0; i < 16; i++) acc[i] = make_float2(0.f, 0.f);

        BAR_ARRIVE(EMPTY0, 512);
        BAR_ARRIVE(EMPTY0 + 1, 512);

        for (int ii = 0; ii < njs; ii++) {
            const int b = ii & 1;
            BAR_SYNC(FULL0 + b, 512);
            float* ps  = psb[b];
            float* scl = sclb[b];
            {
                // scale accumulators by per-query-pair sc (aligned LDS.64)
                #pragma unroll
                for (int pi = 0; pi < 4; pi++) {
                    const float2 scp = *(const float2*)(scl + qbase + 2 * pi);
                    #pragma unroll
                    for (int d = 0; d < 4; d++) fmul2(acc[pi * 4 + d], scp);
                }
                const float* vp0 = vs + 4 * lane;
                #pragma unroll 4
                for (int s = 0; s < 64; s++) {
                    const float4 vv = *(const float4*)(vp0 + s * DV);
                    const float2 vd0 = dup2(vv.x);
                    const float2 vd1 = dup2(vv.y);
                    const float2 vd2 = dup2(vv.z);
                    const float2 vd3 = dup2(vv.w);
                    const float4 pA = *(const float4*)(ps + s * PPAD + qbase);
                    const float4 pB = *(const float4*)(ps + s * PPAD + qbase + 4);
                    const float2 P0 = make_float2(pA.x, pA.y);
                    const float2 P1 = make_float2(pA.z, pA.w);
                    const float2 P2 = make_float2(pB.x, pB.y);
                    const float2 P3 = make_float2(pB.z, pB.w);
                    ffma2(acc[0],  P0, vd0); ffma2(acc[1],  P0, vd1);
                    ffma2(acc[2],  P0, vd2); ffma2(acc[3],  P0, vd3);
                    ffma2(acc[4],  P1, vd0); ffma2(acc[5],  P1, vd1);
                    ffma2(acc[6],  P1, vd2); ffma2(acc[7],  P1, vd3);
                    ffma2(acc[8],  P2, vd0); ffma2(acc[9],  P2, vd1);
                    ffma2(acc[10], P2, vd2); ffma2(acc[11], P2, vd3);
                    ffma2(acc[12], P3, vd0); ffma2(acc[13], P3, vd1);
                    ffma2(acc[14], P3, vd2); ffma2(acc[15], P3, vd3);
                }
            }
            BAR_SYNC(PBAR, 256);
            for (int f = pt; f < (64 * PPAD) / 4; f += 256)
                ((float4*)ps)[f] = make_float4(0.f, 0.f, 0.f, 0.f);
            if (pt < 66) scl[pt] = 1.0f;
            MEMBAR_CTA();
            BAR_ARRIVE(EMPTY0 + b, 512);
            if (ii + 1 < njs) {
                const int jn = jlist[ii + 1];
                const float* vblk = v + ((size_t)(seq0 + jn * 64) * HQ + h) * DV;
                for (int f = pt; f < 64 * (DV / 4); f += 256) {
                    int s = f >> 5, c = f & 31;
                    ((float4*)vs)[s * 32 + c] =
                        ((const float4*)vblk)[(size_t)s * HQ * (DV / 4) + c];
                }
            }
        }

        __syncthreads();
        #pragma unroll
        for (int pi = 0; pi < 4; pi++) {
            const int qa = qbase + 2 * pi;
            const float invla = 1.0f / ls[qa];
            const float invlb = 1.0f / ls[qa + 1];
            float* opa = out + (size_t)(t0 + qa)     * (HQ * DV) + (size_t)h * DV + 4 * lane;
            float* opb = out + (size_t)(t0 + qa + 1) * (HQ * DV) + (size_t)h * DV + 4 * lane;
            float4 oa, ob;
            oa.x = acc[pi * 4 + 0].x * invla; ob.x = acc[pi * 4 + 0].y * invlb;
            oa.y = acc[pi * 4 + 1].x * invla; ob.y = acc[pi * 4 + 1].y * invlb;
            oa.z = acc[pi * 4 + 2].x * invla; ob.z = acc[pi * 4 + 2].y * invlb;
            oa.w = acc[pi * 4 + 3].x * invla; ob.w = acc[pi * 4 + 3].y * invlb;
            *(float4*)opa = oa;
            *(float4*)opb = ob;
        }
        return;
    }
    __syncthreads();   // score group joins PV group's final sync
}

extern "C" void kernel_launch(void* const* d_in, const int* in_sizes, int n_in,
                              void* d_out, int out_size) {
    const float* q   = (const float*)d_in[0];
    const float* k   = (const float*)d_in[1];
    const float* v   = (const float*)d_in[2];
    const int*   idx = (const int*)d_in[3];
    const int*   slp = (n_in >= 6) ? (const int*)d_in[5] : nullptr;
    float* out = (float*)d_out;

    const int T = in_sizes[0] / (HQ * DQK);

    static bool attr_set = false;
    if (!attr_set) {
        cudaFuncSetAttribute(selattn_kernel,
                             cudaFuncAttributeMaxDynamicSharedMemorySize, SMEM_BYTES);
        attr_set = true;
    }

    dim3 grid(T / QT, HQ);
    selattn_kernel<<<grid, THREADS, SMEM_BYTES>>>(q, k, v, idx, slp, out);
}

// round 14
// speedup vs baseline: 2.4437x; 1.1393x over previous
#include <cuda_runtime.h>
#include <cuda_bf16.h>
#include <cstdint>
#include <stdint.h>
#include <math.h>
#include <string.h>

#define HQ 16
#define GRP 4
#define TOPK 16
#define DQK 192
#define DV 128
#define QT 64
#define THREADS 512
#define PPAD 68
#define NBITS 32
#define SMSCALE 0.07216878364870322f
#define XROW 392              // bf16 row: 384 data + 8 pad (784B = 49*16, LDSM conflict-free)

// byte offsets in 1KB-aligned smem window
#define QX_OFF   0            // [64][392] bf16 = 50176
#define KX0_OFF  50176
#define KX1_OFF  100352
#define VS_OFF   150528       // [64][128] f32 = 32768
#define PS0_OFF  183296       // [64][68] f32 = 17408
#define PS1_OFF  200704
#define LS_OFF   218112       // [64] f32
#define SELM_OFF 218368       // [64] u32
#define JL_OFF   218624       // [33] int
#define NJS_OFF  218756
#define SMEM_BYTES (218760 + 1024)

#define FULL0  1
#define EMPTY0 3
#define SBAR   5
#define PBAR   6
#define BAR_SYNC(id, cnt)   asm volatile("bar.sync %0, %1;"   :: "r"(id), "r"(cnt) : "memory")
#define BAR_ARRIVE(id, cnt) asm volatile("bar.arrive %0, %1;" :: "r"(id), "r"(cnt) : "memory")
#define MEMBAR_CTA()        asm volatile("membar.cta;" ::: "memory")

__device__ __forceinline__ void ffma2(float2& d, const float2 a, const float2 b) {
    unsigned long long ua, ub;
    memcpy(&ua, &a, 8); memcpy(&ub, &b, 8);
    unsigned long long* pd = reinterpret_cast<unsigned long long*>(&d);
    asm("fma.rn.f32x2 %0, %1, %2, %0;" : "+l"(*pd) : "l"(ua), "l"(ub));
}
__device__ __forceinline__ float2 dup2(float x) {
    float2 r;
    unsigned long long* pr = reinterpret_cast<unsigned long long*>(&r);
    asm("mov.b64 %0, {%1, %1};" : "=l"(*pr) : "f"(x));
    return r;
}
__device__ __forceinline__ uint32_t smem_u32(const void* p) {
    return (uint32_t)__cvta_generic_to_shared(p);
}
#define LDSM_X4(r0, r1, r2, r3, addr) \
    asm volatile("ldmatrix.sync.aligned.m8n8.x4.shared.b16 {%0,%1,%2,%3}, [%4];" \
        : "=r"(r0), "=r"(r1), "=r"(r2), "=r"(r3) : "r"(addr))
#define MMA_BF16(c, a0, a1, a2, a3, b0, b1) \
    asm volatile("mma.sync.aligned.m16n8k16.row.col.f32.bf16.bf16.f32 " \
        "{%0,%1,%2,%3}, {%4,%5,%6,%7}, {%8,%9}, {%0,%1,%2,%3};" \
        : "+f"((c)[0]), "+f"((c)[1]), "+f"((c)[2]), "+f"((c)[3]) \
        : "r"(a0), "r"(a1), "r"(a2), "r"(a3), "r"(b0), "r"(b1))

__global__ __launch_bounds__(THREADS, 1)
void selattn_kernel(const float* __restrict__ q, const float* __restrict__ k,
                    const float* __restrict__ v, const int* __restrict__ sidx,
                    const int* __restrict__ slp, float* __restrict__ out) {
    extern __shared__ char shraw[];
    char* sm = (char*)(((uintptr_t)shraw + 1023) & ~(uintptr_t)1023);
    float* vs  = (float*)(sm + VS_OFF);
    float* psb[2] = {(float*)(sm + PS0_OFF), (float*)(sm + PS1_OFF)};
    float* ls  = (float*)(sm + LS_OFF);
    unsigned* selm = (unsigned*)(sm + SELM_OFF);
    int* jlist = (int*)(sm + JL_OFF);
    int* njsp  = (int*)(sm + NJS_OFF);

    const int S    = slp ? slp[0] : 2048;
    const int qt   = blockIdx.x;
    const int h    = blockIdx.y;
    const int g    = h >> 2;
    const int t0   = qt * QT;
    const int seq0 = (t0 / S) * S;
    const int tid  = threadIdx.x;
    const int lane = tid & 31;
    const int w    = tid >> 5;

    // ---- selection masks / jlist / ls init ----
    if (tid < QT) { selm[tid] = 0u; ls[tid] = 0.0f; }
    __syncthreads();
    for (int f = tid; f < QT * TOPK; f += THREADS) {
        int qi = f >> 4, kk = f & 15;
        int b = sidx[(size_t)(t0 + qi) * (GRP * TOPK) + g * TOPK + kk] & 31;
        atomicOr(&selm[qi], 1u << b);
    }
    __syncthreads();
    if (tid < QT) {
        int tq = (t0 + tid) - seq0;
        int bt = tq >> 6;
        unsigned causal = (bt >= 31) ? 0xffffffffu : ((1u << (bt + 1)) - 1u);
        selm[tid] &= causal;
    }
    __syncthreads();
    if (tid == 0) {
        unsigned u = 0;
        #pragma unroll
        for (int i = 0; i < QT; i++) u |= selm[i];
        int n = 0;
        for (int j = 0; j < NBITS; j++)
            if ((u >> j) & 1u) jlist[n++] = j;
        *njsp = n;
    }
    __syncthreads();
    const int njs = *njsp;

    // ---- hi/lo bf16 fill: row-major [64][392], hi at cols 0-191, lo at 192-383 ----
    auto fill_tile = [&](char* dst, const float* grow, size_t rstride,
                         int tl, int nth) {
        for (int f = tl; f < 64 * 96; f += nth) {
            int r = f / 96, dp = f - r * 96;
            int d = dp * 2;
            float2 kv = *(const float2*)(grow + (size_t)r * rstride + d);
            __nv_bfloat16 h0 = __float2bfloat16(kv.x);
            __nv_bfloat16 h1 = __float2bfloat16(kv.y);
            __nv_bfloat16 l0 = __float2bfloat16(kv.x - __bfloat162float(h0));
            __nv_bfloat16 l1 = __float2bfloat16(kv.y - __bfloat162float(h1));
            __nv_bfloat162 hh = __halves2bfloat162(h0, h1);
            __nv_bfloat162 ll = __halves2bfloat162(l0, l1);
            char* row = dst + (size_t)r * (XROW * 2);
            *(uint32_t*)(row + d * 2)         = *(uint32_t*)&hh;
            *(uint32_t*)(row + (192 + d) * 2) = *(uint32_t*)&ll;
        }
    };

    // ---- prologue fills: Qx, Kx0, Kx1, vs ----
    fill_tile(sm + QX_OFF, q + (size_t)t0 * HQ * DQK + (size_t)h * DQK,
              (size_t)HQ * DQK, tid, THREADS);
    {
        const int j0 = jlist[0];
        fill_tile(sm + KX0_OFF, k + ((size_t)(seq0 + j0 * 64) * HQ + h) * DQK,
                  (size_t)HQ * DQK, tid, THREADS);
        if (njs > 1) {
            const int j1 = jlist[1];
            fill_tile(sm + KX1_OFF, k + ((size_t)(seq0 + j1 * 64) * HQ + h) * DQK,
                      (size_t)HQ * DQK, tid, THREADS);
        }
        const float* vblk = v + ((size_t)(seq0 + jlist[0] * 64) * HQ + h) * DV;
        for (int f = tid; f < 64 * (DV / 4); f += THREADS) {
            int s = f >> 5, c = f & 31;
            ((float4*)vs)[s * 32 + c] =
                ((const float4*)vblk)[(size_t)s * HQ * (DV / 4) + c];
        }
    }
    __syncthreads();

    if (w < 8) {
        // ========= SCORE GROUP (w0-7): 3-term HMMA QK^T + m=0 softmax + Kx fills =========
        const int m0    = (w >> 1) * 16;          // warp's 16 query rows
        const int nhalf = (w & 1) * 32;           // warp's 32 kv cols
        const uint32_t qx_base = smem_u32(sm + QX_OFF)
            + (uint32_t)(m0 + (lane & 15)) * (XROW * 2) + (uint32_t)((lane >> 4) << 4);
        const uint32_t kb_row = (uint32_t)(nhalf + (lane & 7) + ((lane >> 4) << 3)) * (XROW * 2)
                              + (uint32_t)(((lane >> 3) & 1) << 4);
        const int r0 = m0 + (lane >> 2);
        const int r1 = r0 + 8;
        const int tq0 = t0 + r0 - seq0;
        const int tq1 = t0 + r1 - seq0;
        const int st256 = tid;
        const uint32_t LO = 384u;                 // byte offset of lo half (192 bf16)

        for (int ii = 0; ii < njs; ii++) {
            const int b = ii & 1;
            const int j = jlist[ii];
            BAR_SYNC(EMPTY0 + b, 512);            // ps[b] free
            float* ps = psb[b];
            const uint32_t kx = smem_u32(sm + (b ? KX1_OFF : KX0_OFF));

            float c[4][4];
            #pragma unroll
            for (int nt = 0; nt < 4; nt++)
                #pragma unroll
                for (int i = 0; i < 4; i++) c[nt][i] = 0.0f;

            // 3 term groups x 12 k-steps: (qh,kh), (qh,kl), (ql,kh)
            #pragma unroll
            for (int grp = 0; grp < 3; grp++) {
                const uint32_t aoff = (grp == 2) ? LO : 0u;
                const uint32_t boff = (grp == 1) ? LO : 0u;
                #pragma unroll 4
                for (int st = 0; st < 12; st++) {
                    const uint32_t koff = (uint32_t)st * 32;
                    uint32_t a0, a1, a2, a3;
                    LDSM_X4(a0, a1, a2, a3, qx_base + aoff + koff);
                    uint32_t b00, b01, b10, b11;
                    LDSM_X4(b00, b01, b10, b11, kx + kb_row + boff + koff);
                    uint32_t b20, b21, b30, b31;
                    LDSM_X4(b20, b21, b30, b31,
                            kx + kb_row + (uint32_t)16 * (XROW * 2) + boff + koff);
                    MMA_BF16(c[0], a0, a1, a2, a3, b00, b01);
                    MMA_BF16(c[1], a0, a1, a2, a3, b10, b11);
                    MMA_BF16(c[2], a0, a1, a2, a3, b20, b21);
                    MMA_BF16(c[3], a0, a1, a2, a3, b30, b31);
                }
            }

            // m=0 softmax in fragments
            const unsigned sel0 = (selm[r0] >> j) & 1u;
            const unsigned sel1 = (selm[r1] >> j) & 1u;
            float rsum0 = 0.0f, rsum1 = 0.0f;
            #pragma unroll
            for (int nt = 0; nt < 4; nt++) {
                const int col = nhalf + nt * 8 + 2 * (lane & 3);
                const int gc0 = j * 64 + col;
                float p00 = (sel0 && gc0     <= tq0) ? __expf(c[nt][0] * SMSCALE) : 0.0f;
                float p01 = (sel0 && gc0 + 1 <= tq0) ? __expf(c[nt][1] * SMSCALE) : 0.0f;
                float p10 = (sel1 && gc0     <= tq1) ? __expf(c[nt][2] * SMSCALE) : 0.0f;
                float p11 = (sel1 && gc0 + 1 <= tq1) ? __expf(c[nt][3] * SMSCALE) : 0.0f;
                rsum0 += p00 + p01;
                rsum1 += p10 + p11;
                ps[(col)     * PPAD + r0] = p00;
                ps[(col + 1) * PPAD + r0] = p01;
                ps[(col)     * PPAD + r1] = p10;
                ps[(col + 1) * PPAD + r1] = p11;
            }
            rsum0 += __shfl_xor_sync(0xffffffffu, rsum0, 1);
            rsum0 += __shfl_xor_sync(0xffffffffu, rsum0, 2);
            rsum1 += __shfl_xor_sync(0xffffffffu, rsum1, 1);
            rsum1 += __shfl_xor_sync(0xffffffffu, rsum1, 2);
            if ((lane & 3) == 0) {
                atomicAdd(&ls[r0], rsum0);
                atomicAdd(&ls[r1], rsum1);
            }
            MEMBAR_CTA();
            BAR_ARRIVE(FULL0 + b, 512);           // ps[b] ready for PV
            BAR_SYNC(SBAR, 256);                  // score warps done reading kx[b]
            if (ii + 2 < njs) {
                const int jn = jlist[ii + 2];
                fill_tile(sm + (b ? KX1_OFF : KX0_OFF),
                          k + ((size_t)(seq0 + jn * 64) * HQ + h) * DQK,
                          (size_t)HQ * DQK, st256, 256);
            }
        }
        BAR_SYNC(EMPTY0 + (njs & 1), 512);
        BAR_SYNC(EMPTY0 + ((njs + 1) & 1), 512);
        __syncthreads();
    } else {
        // ========= PV GROUP (w8-15): pure accumulate =========
        const int pt = tid - 256;
        const int qbase = (w - 8) * 8;
        float2 acc[16];
        #pragma unroll
        for (int i = 0; i < 16; i++) acc[i] = make_float2(0.f, 0.f);

        BAR_ARRIVE(EMPTY0, 512);
        BAR_ARRIVE(EMPTY0 + 1, 512);

        for (int ii = 0; ii < njs; ii++) {
            const int b = ii & 1;
            BAR_SYNC(FULL0 + b, 512);
            float* ps = psb[b];
            const float* vp0 = vs + 4 * lane;
            #pragma unroll 4
            for (int s = 0; s < 64; s++) {
                const float4 vv = *(const float4*)(vp0 + s * DV);
                const float2 vd0 = dup2(vv.x);
                const float2 vd1 = dup2(vv.y);
                const float2 vd2 = dup2(vv.z);
                const float2 vd3 = dup2(vv.w);
                const float4 pA = *(const float4*)(ps + s * PPAD + qbase);
                const float4 pB = *(const float4*)(ps + s * PPAD + qbase + 4);
                const float2 P0 = make_float2(pA.x, pA.y);
                const float2 P1 = make_float2(pA.z, pA.w);
                const float2 P2 = make_float2(pB.x, pB.y);
                const float2 P3 = make_float2(pB.z, pB.w);
                ffma2(acc[0],  P0, vd0); ffma2(acc[1],  P0, vd1);
                ffma2(acc[2],  P0, vd2); ffma2(acc[3],  P0, vd3);
                ffma2(acc[4],  P1, vd0); ffma2(acc[5],  P1, vd1);
                ffma2(acc[6],  P1, vd2); ffma2(acc[7],  P1, vd3);
                ffma2(acc[8],  P2, vd0); ffma2(acc[9],  P2, vd1);
                ffma2(acc[10], P2, vd2); ffma2(acc[11], P2, vd3);
                ffma2(acc[12], P3, vd0); ffma2(acc[13], P3, vd1);
                ffma2(acc[14], P3, vd2); ffma2(acc[15], P3, vd3);
            }
            BAR_SYNC(PBAR, 256);
            BAR_ARRIVE(EMPTY0 + b, 512);
            if (ii + 1 < njs) {
                const int jn = jlist[ii + 1];
                const float* vblk = v + ((size_t)(seq0 + jn * 64) * HQ + h) * DV;
                for (int f = pt; f < 64 * (DV / 4); f += 256) {
                    int s = f >> 5, c = f & 31;
                    ((float4*)vs)[s * 32 + c] =
                        ((const float4*)vblk)[(size_t)s * HQ * (DV / 4) + c];
                }
            }
        }
        __syncthreads();
        #pragma unroll
        for (int pi = 0; pi < 4; pi++) {
            const int qa = qbase + 2 * pi;
            const float invla = 1.0f / ls[qa];
            const float invlb = 1.0f / ls[qa + 1];
            float* opa = out + (size_t)(t0 + qa)     * (HQ * DV) + (size_t)h * DV + 4 * lane;
            float* opb = out + (size_t)(t0 + qa + 1) * (HQ * DV) + (size_t)h * DV + 4 * lane;
            float4 oa, ob;
            oa.x = acc[pi * 4 + 0].x * invla; ob.x = acc[pi * 4 + 0].y * invlb;
            oa.y = acc[pi * 4 + 1].x * invla; ob.y = acc[pi * 4 + 1].y * invlb;
            oa.z = acc[pi * 4 + 2].x * invla; ob.z = acc[pi * 4 + 2].y * invlb;
            oa.w = acc[pi * 4 + 3].x * invla; ob.w = acc[pi * 4 + 3].y * invlb;
            *(float4*)opa = oa;
            *(float4*)opb = ob;
        }
    }
}

extern "C" void kernel_launch(void* const* d_in, const int* in_sizes, int n_in,
                              void* d_out, int out_size) {
    const float* q   = (const float*)d_in[0];
    const float* k   = (const float*)d_in[1];
    const float* v   = (const float*)d_in[2];
    const int*   idx = (const int*)d_in[3];
    const int*   slp = (n_in >= 6) ? (const int*)d_in[5] : nullptr;
    float* out = (float*)d_out;

    const int T = in_sizes[0] / (HQ * DQK);

    static bool attr_set = false;
    if (!attr_set) {
        cudaFuncSetAttribute(selattn_kernel,
                             cudaFuncAttributeMaxDynamicSharedMemorySize, SMEM_BYTES);
        attr_set = true;
    }

    dim3 grid(T / QT, HQ);
    selattn_kernel<<<grid, THREADS, SMEM_BYTES>>>(q, k, v, idx, slp, out);
}

// round 15
// speedup vs baseline: 2.5770x; 1.0545x over previous
#include <cuda_runtime.h>
#include <cuda_bf16.h>
#include <cstdint>
#include <stdint.h>
#include <math.h>
#include <string.h>

#define HQ 16
#define GRP 4
#define TOPK 16
#define DQK 192
#define DV 128
#define QT 64
#define THREADS 512
#define PPAD 68
#define NBITS 32
#define SMSCALE 0.07216878364870322f
#define XROW 392              // bf16 row: 384 data + 8 pad (784B = 49*16, LDSM conflict-free)
#define ROW16 (16 * XROW * 2) // byte stride of 16 rows
#define LOOFF 384u            // byte offset of lo half (192 bf16)

// byte offsets in 1KB-aligned smem window
#define QX_OFF   0            // [64][392] bf16 = 50176
#define KX0_OFF  50176
#define KX1_OFF  100352
#define VS_OFF   150528       // [64][128] f32 = 32768
#define PS0_OFF  183296       // [64][68] f32 = 17408
#define PS1_OFF  200704
#define LS_OFF   218112       // [64] f32
#define SELM_OFF 218368       // [64] u32
#define JL_OFF   218624       // [33] int
#define NJS_OFF  218756
#define SMEM_BYTES (218760 + 1024)

#define FULL0  1
#define EMPTY0 3
#define SBAR   5
#define PBAR   6
#define BAR_SYNC(id, cnt)   asm volatile("bar.sync %0, %1;"   :: "r"(id), "r"(cnt) : "memory")
#define BAR_ARRIVE(id, cnt) asm volatile("bar.arrive %0, %1;" :: "r"(id), "r"(cnt) : "memory")
#define MEMBAR_CTA()        asm volatile("membar.cta;" ::: "memory")

__device__ __forceinline__ void ffma2(float2& d, const float2 a, const float2 b) {
    unsigned long long ua, ub;
    memcpy(&ua, &a, 8); memcpy(&ub, &b, 8);
    unsigned long long* pd = reinterpret_cast<unsigned long long*>(&d);
    asm("fma.rn.f32x2 %0, %1, %2, %0;" : "+l"(*pd) : "l"(ua), "l"(ub));
}
__device__ __forceinline__ float2 dup2(float x) {
    float2 r;
    unsigned long long* pr = reinterpret_cast<unsigned long long*>(&r);
    asm("mov.b64 %0, {%1, %1};" : "=l"(*pr) : "f"(x));
    return r;
}
__device__ __forceinline__ uint32_t smem_u32(const void* p) {
    return (uint32_t)__cvta_generic_to_shared(p);
}
#define LDSM_X4(r0, r1, r2, r3, addr) \
    asm volatile("ldmatrix.sync.aligned.m8n8.x4.shared.b16 {%0,%1,%2,%3}, [%4];" \
        : "=r"(r0), "=r"(r1), "=r"(r2), "=r"(r3) : "r"(addr))
#define MMA_BF16(c, a0, a1, a2, a3, b0, b1) \
    asm volatile("mma.sync.aligned.m16n8k16.row.col.f32.bf16.bf16.f32 " \
        "{%0,%1,%2,%3}, {%4,%5,%6,%7}, {%8,%9}, {%0,%1,%2,%3};" \
        : "+f"((c)[0]), "+f"((c)[1]), "+f"((c)[2]), "+f"((c)[3]) \
        : "r"(a0), "r"(a1), "r"(a2), "r"(a3), "r"(b0), "r"(b1))

__global__ __launch_bounds__(THREADS, 1)
void selattn_kernel(const float* __restrict__ q, const float* __restrict__ k,
                    const float* __restrict__ v, const int* __restrict__ sidx,
                    const int* __restrict__ slp, float* __restrict__ out) {
    extern __shared__ char shraw[];
    char* sm = (char*)(((uintptr_t)shraw + 1023) & ~(uintptr_t)1023);
    float* vs  = (float*)(sm + VS_OFF);
    float* psb[2] = {(float*)(sm + PS0_OFF), (float*)(sm + PS1_OFF)};
    float* ls  = (float*)(sm + LS_OFF);
    unsigned* selm = (unsigned*)(sm + SELM_OFF);
    int* jlist = (int*)(sm + JL_OFF);
    int* njsp  = (int*)(sm + NJS_OFF);

    const int S    = slp ? slp[0] : 2048;
    const int qt   = blockIdx.x;
    const int h    = blockIdx.y;
    const int g    = h >> 2;
    const int t0   = qt * QT;
    const int seq0 = (t0 / S) * S;
    const int tid  = threadIdx.x;
    const int lane = tid & 31;
    const int w    = tid >> 5;

    // ---- selection masks / jlist / ls init ----
    if (tid < QT) { selm[tid] = 0u; ls[tid] = 0.0f; }
    __syncthreads();
    for (int f = tid; f < QT * TOPK; f += THREADS) {
        int qi = f >> 4, kk = f & 15;
        int b = sidx[(size_t)(t0 + qi) * (GRP * TOPK) + g * TOPK + kk] & 31;
        atomicOr(&selm[qi], 1u << b);
    }
    __syncthreads();
    if (tid < QT) {
        int tq = (t0 + tid) - seq0;
        int bt = tq >> 6;
        unsigned causal = (bt >= 31) ? 0xffffffffu : ((1u << (bt + 1)) - 1u);
        selm[tid] &= causal;
    }
    __syncthreads();
    if (tid == 0) {
        unsigned u = 0;
        #pragma unroll
        for (int i = 0; i < QT; i++) u |= selm[i];
        int n = 0;
        for (int j = 0; j < NBITS; j++)
            if ((u >> j) & 1u) jlist[n++] = j;
        *njsp = n;
    }
    __syncthreads();
    const int njs = *njsp;

    // ---- hi/lo bf16 fill: row-major [64][392], hi at cols 0-191, lo at 192-383 ----
    auto fill_tile = [&](char* dst, const float* grow, size_t rstride,
                         int tl, int nth) {
        for (int f = tl; f < 64 * 96; f += nth) {
            int r = f / 96, dp = f - r * 96;
            int d = dp * 2;
            float2 kv = *(const float2*)(grow + (size_t)r * rstride + d);
            __nv_bfloat16 h0 = __float2bfloat16(kv.x);
            __nv_bfloat16 h1 = __float2bfloat16(kv.y);
            __nv_bfloat16 l0 = __float2bfloat16(kv.x - __bfloat162float(h0));
            __nv_bfloat16 l1 = __float2bfloat16(kv.y - __bfloat162float(h1));
            __nv_bfloat162 hh = __halves2bfloat162(h0, h1);
            __nv_bfloat162 ll = __halves2bfloat162(l0, l1);
            char* row = dst + (size_t)r * (XROW * 2);
            *(uint32_t*)(row + d * 2)         = *(uint32_t*)&hh;
            *(uint32_t*)(row + (192 + d) * 2) = *(uint32_t*)&ll;
        }
    };

    // ---- prologue fills: Qx, Kx0, Kx1, vs ----
    fill_tile(sm + QX_OFF, q + (size_t)t0 * HQ * DQK + (size_t)h * DQK,
              (size_t)HQ * DQK, tid, THREADS);
    {
        const int j0 = jlist[0];
        fill_tile(sm + KX0_OFF, k + ((size_t)(seq0 + j0 * 64) * HQ + h) * DQK,
                  (size_t)HQ * DQK, tid, THREADS);
        if (njs > 1) {
            const int j1 = jlist[1];
            fill_tile(sm + KX1_OFF, k + ((size_t)(seq0 + j1 * 64) * HQ + h) * DQK,
                      (size_t)HQ * DQK, tid, THREADS);
        }
        const float* vblk = v + ((size_t)(seq0 + jlist[0] * 64) * HQ + h) * DV;
        for (int f = tid; f < 64 * (DV / 4); f += THREADS) {
            int s = f >> 5, c = f & 31;
            ((float4*)vs)[s * 32 + c] =
                ((const float4*)vblk)[(size_t)s * HQ * (DV / 4) + c];
        }
    }
    __syncthreads();

    if (w < 8) {
        // ===== SCORE GROUP (w0-7): fused 3-term HMMA + warp-level block skip =====
        const int m0    = (w >> 1) * 16;          // warp's 16 query rows
        const int nhalf = (w & 1) * 32;           // warp's 32 kv cols
        const uint32_t qx_base = smem_u32(sm + QX_OFF)
            + (uint32_t)(m0 + (lane & 15)) * (XROW * 2) + (uint32_t)((lane >> 4) << 4);
        const uint32_t kb_row = (uint32_t)(nhalf + (lane & 7) + ((lane >> 4) << 3)) * (XROW * 2)
                              + (uint32_t)(((lane >> 3) & 1) << 4);
        const int r0 = m0 + (lane >> 2);
        const int r1 = r0 + 8;
        const int tq0 = t0 + r0 - seq0;
        const int tq1 = t0 + r1 - seq0;
        const int st256 = tid;

        unsigned wsel = 0;                        // union over this warp's 16 queries
        #pragma unroll
        for (int i = 0; i < 16; i++) wsel |= selm[m0 + i];

        for (int ii = 0; ii < njs; ii++) {
            const int b = ii & 1;
            const int j = jlist[ii];
            BAR_SYNC(EMPTY0 + b, 512);            // ps[b] free
            float* ps = psb[b];

            if ((wsel >> j) & 1u) {
                const uint32_t kx = smem_u32(sm + (b ? KX1_OFF : KX0_OFF));
                float c[4][4];
                #pragma unroll
                for (int nt = 0; nt < 4; nt++)
                    #pragma unroll
                    for (int i = 0; i < 4; i++) c[nt][i] = 0.0f;

                // fused 12 k-steps: each loads qh,ql,kh(2),kl(2) once; 12 MMA/step
                #pragma unroll 2
                for (int st = 0; st < 12; st++) {
                    const uint32_t koff = (uint32_t)st * 32;
                    uint32_t ah0, ah1, ah2, ah3, al0, al1, al2, al3;
                    LDSM_X4(ah0, ah1, ah2, ah3, qx_base + koff);
                    LDSM_X4(al0, al1, al2, al3, qx_base + LOOFF + koff);
                    uint32_t bh00, bh01, bh10, bh11, bh20, bh21, bh30, bh31;
                    LDSM_X4(bh00, bh01, bh10, bh11, kx + kb_row + koff);
                    LDSM_X4(bh20, bh21, bh30, bh31, kx + kb_row + ROW16 + koff);
                    uint32_t bl00, bl01, bl10, bl11, bl20, bl21, bl30, bl31;
                    LDSM_X4(bl00, bl01, bl10, bl11, kx + kb_row + LOOFF + koff);
                    LDSM_X4(bl20, bl21, bl30, bl31, kx + kb_row + ROW16 + LOOFF + koff);
                    // qh x kh
                    MMA_BF16(c[0], ah0, ah1, ah2, ah3, bh00, bh01);
                    MMA_BF16(c[1], ah0, ah1, ah2, ah3, bh10, bh11);
                    MMA_BF16(c[2], ah0, ah1, ah2, ah3, bh20, bh21);
                    MMA_BF16(c[3], ah0, ah1, ah2, ah3, bh30, bh31);
                    // qh x kl
                    MMA_BF16(c[0], ah0, ah1, ah2, ah3, bl00, bl01);
                    MMA_BF16(c[1], ah0, ah1, ah2, ah3, bl10, bl11);
                    MMA_BF16(c[2], ah0, ah1, ah2, ah3, bl20, bl21);
                    MMA_BF16(c[3], ah0, ah1, ah2, ah3, bl30, bl31);
                    // ql x kh
                    MMA_BF16(c[0], al0, al1, al2, al3, bh00, bh01);
                    MMA_BF16(c[1], al0, al1, al2, al3, bh10, bh11);
                    MMA_BF16(c[2], al0, al1, al2, al3, bh20, bh21);
                    MMA_BF16(c[3], al0, al1, al2, al3, bh30, bh31);
                }

                // m=0 softmax in fragments
                const unsigned sel0 = (selm[r0] >> j) & 1u;
                const unsigned sel1 = (selm[r1] >> j) & 1u;
                float rsum0 = 0.0f, rsum1 = 0.0f;
                #pragma unroll
                for (int nt = 0; nt < 4; nt++) {
                    const int col = nhalf + nt * 8 + 2 * (lane & 3);
                    const int gc0 = j * 64 + col;
                    float p00 = (sel0 && gc0     <= tq0) ? __expf(c[nt][0] * SMSCALE) : 0.0f;
                    float p01 = (sel0 && gc0 + 1 <= tq0) ? __expf(c[nt][1] * SMSCALE) : 0.0f;
                    float p10 = (sel1 && gc0     <= tq1) ? __expf(c[nt][2] * SMSCALE) : 0.0f;
                    float p11 = (sel1 && gc0 + 1 <= tq1) ? __expf(c[nt][3] * SMSCALE) : 0.0f;
                    rsum0 += p00 + p01;
                    rsum1 += p10 + p11;
                    ps[(col)     * PPAD + r0] = p00;
                    ps[(col + 1) * PPAD + r0] = p01;
                    ps[(col)     * PPAD + r1] = p10;
                    ps[(col + 1) * PPAD + r1] = p11;
                }
                rsum0 += __shfl_xor_sync(0xffffffffu, rsum0, 1);
                rsum0 += __shfl_xor_sync(0xffffffffu, rsum0, 2);
                rsum1 += __shfl_xor_sync(0xffffffffu, rsum1, 1);
                rsum1 += __shfl_xor_sync(0xffffffffu, rsum1, 2);
                if ((lane & 3) == 0) {
                    atomicAdd(&ls[r0], rsum0);
                    atomicAdd(&ls[r1], rsum1);
                }
            } else {
                // no query in this warp's 16 selects block j: zero our ps columns
                #pragma unroll
                for (int nt = 0; nt < 4; nt++) {
                    const int col = nhalf + nt * 8 + 2 * (lane & 3);
                    ps[(col)     * PPAD + r0] = 0.0f;
                    ps[(col + 1) * PPAD + r0] = 0.0f;
                    ps[(col)     * PPAD + r1] = 0.0f;
                    ps[(col + 1) * PPAD + r1] = 0.0f;
                }
            }
            MEMBAR_CTA();
            BAR_ARRIVE(FULL0 + b, 512);           // ps[b] ready for PV
            BAR_SYNC(SBAR, 256);                  // score warps done reading kx[b]
            if (ii + 2 < njs) {
                const int jn = jlist[ii + 2];
                fill_tile(sm + (b ? KX1_OFF : KX0_OFF),
                          k + ((size_t)(seq0 + jn * 64) * HQ + h) * DQK,
                          (size_t)HQ * DQK, st256, 256);
            }
        }
        BAR_SYNC(EMPTY0 + (njs & 1), 512);
        BAR_SYNC(EMPTY0 + ((njs + 1) & 1), 512);
        __syncthreads();
    } else {
        // ========= PV GROUP (w8-15): pure accumulate =========
        const int pt = tid - 256;
        const int qbase = (w - 8) * 8;
        float2 acc[16];
        #pragma unroll
        for (int i = 0; i < 16; i++) acc[i] = make_float2(0.f, 0.f);

        BAR_ARRIVE(EMPTY0, 512);
        BAR_ARRIVE(EMPTY0 + 1, 512);

        for (int ii = 0; ii < njs; ii++) {
            const int b = ii & 1;
            BAR_SYNC(FULL0 + b, 512);
            float* ps = psb[b];
            const float* vp0 = vs + 4 * lane;
            #pragma unroll 4
            for (int s = 0; s < 64; s++) {
                const float4 vv = *(const float4*)(vp0 + s * DV);
                const float2 vd0 = dup2(vv.x);
                const float2 vd1 = dup2(vv.y);
                const float2 vd2 = dup2(vv.z);
                const float2 vd3 = dup2(vv.w);
                const float4 pA = *(const float4*)(ps + s * PPAD + qbase);
                const float4 pB = *(const float4*)(ps + s * PPAD + qbase + 4);
                const float2 P0 = make_float2(pA.x, pA.y);
                const float2 P1 = make_float2(pA.z, pA.w);
                const float2 P2 = make_float2(pB.x, pB.y);
                const float2 P3 = make_float2(pB.z, pB.w);
                ffma2(acc[0],  P0, vd0); ffma2(acc[1],  P0, vd1);
                ffma2(acc[2],  P0, vd2); ffma2(acc[3],  P0, vd3);
                ffma2(acc[4],  P1, vd0); ffma2(acc[5],  P1, vd1);
                ffma2(acc[6],  P1, vd2); ffma2(acc[7],  P1, vd3);
                ffma2(acc[8],  P2, vd0); ffma2(acc[9],  P2, vd1);
                ffma2(acc[10], P2, vd2); ffma2(acc[11], P2, vd3);
                ffma2(acc[12], P3, vd0); ffma2(acc[13], P3, vd1);
                ffma2(acc[14], P3, vd2); ffma2(acc[15], P3, vd3);
            }
            BAR_SYNC(PBAR, 256);
            BAR_ARRIVE(EMPTY0 + b, 512);
            if (ii + 1 < njs) {
                const int jn = jlist[ii + 1];
                const float* vblk = v + ((size_t)(seq0 + jn * 64) * HQ + h) * DV;
                for (int f = pt; f < 64 * (DV / 4); f += 256) {
                    int s = f >> 5, c = f & 31;
                    ((float4*)vs)[s * 32 + c] =
                        ((const float4*)vblk)[(size_t)s * HQ * (DV / 4) + c];
                }
            }
        }
        __syncthreads();
        #pragma unroll
        for (int pi = 0; pi < 4; pi++) {
            const int qa = qbase + 2 * pi;
            const float invla = 1.0f / ls[qa];
            const float invlb = 1.0f / ls[qa + 1];
            float* opa = out + (size_t)(t0 + qa)     * (HQ * DV) + (size_t)h * DV + 4 * lane;
            float* opb = out + (size_t)(t0 + qa + 1) * (HQ * DV) + (size_t)h * DV + 4 * lane;
            float4 oa, ob;
            oa.x = acc[pi * 4 + 0].x * invla; ob.x = acc[pi * 4 + 0].y * invlb;
            oa.y = acc[pi * 4 + 1].x * invla; ob.y = acc[pi * 4 + 1].y * invlb;
            oa.z = acc[pi * 4 + 2].x * invla; ob.z = acc[pi * 4 + 2].y * invlb;
            oa.w = acc[pi * 4 + 3].x * invla; ob.w = acc[pi * 4 + 3].y * invlb;
            *(float4*)opa = oa;
            *(float4*)opb = ob;
        }
    }
}

extern "C" void kernel_launch(void* const* d_in, const int* in_sizes, int n_in,
                              void* d_out, int out_size) {
    const float* q   = (const float*)d_in[0];
    const float* k   = (const float*)d_in[1];
    const float* v   = (const float*)d_in[2];
    const int*   idx = (const int*)d_in[3];
    const int*   slp = (n_in >= 6) ? (const int*)d_in[5] : nullptr;
    float* out = (float*)d_out;

    const int T = in_sizes[0] / (HQ * DQK);

    static bool attr_set = false;
    if (!attr_set) {
        cudaFuncSetAttribute(selattn_kernel,
                             cudaFuncAttributeMaxDynamicSharedMemorySize, SMEM_BYTES);
        attr_set = true;
    }

    dim3 grid(T / QT, HQ);
    selattn_kernel<<<grid, THREADS, SMEM_BYTES>>>(q, k, v, idx, slp, out);
}

// round 16
// speedup vs baseline: 3.0296x; 1.1756x over previous
#include <cuda_runtime.h>
#include <cuda_bf16.h>
#include <cstdint>
#include <stdint.h>
#include <math.h>
#include <string.h>

#define HQ 16
#define GRP 4
#define TOPK 16
#define DQK 192
#define DV 128
#define QT 64
#define THREADS 512
#define NBITS 32
#define SMSCALE 0.07216878364870322f
#define XROW 392              // Q/K bf16 row: 384 data + 8 pad (784B = 49*16)
#define ROW16 (16 * XROW * 2)
#define LOOFF 384u            // Q/K lo-half byte offset
#define PSP 272               // ps row pitch bytes: 128 ph | 128 pl | 16 pad (17*16)
#define VXP 528               // vx row pitch bytes: 256 vh | 256 vl | 16 pad (33*16)

// byte offsets in 1KB-aligned smem window
#define QX_OFF   0            // [64][784]  = 50176
#define KX0_OFF  50176
#define KX1_OFF  100352
#define VX_OFF   150528       // [64][528]  = 33792
#define PS0_OFF  184320       // [64][272]  = 17408
#define PS1_OFF  201728
#define LS_OFF   219136       // [64] f32
#define SELM_OFF 219392       // [64] u32
#define JL_OFF   219648       // [33] int
#define NJS_OFF  219780
#define SMEM_BYTES (219784 + 1024)

#define FULL0  1
#define EMPTY0 3
#define SBAR   5
#define PBAR   6
#define BAR_SYNC(id, cnt)   asm volatile("bar.sync %0, %1;"   :: "r"(id), "r"(cnt) : "memory")
#define BAR_ARRIVE(id, cnt) asm volatile("bar.arrive %0, %1;" :: "r"(id), "r"(cnt) : "memory")
#define MEMBAR_CTA()        asm volatile("membar.cta;" ::: "memory")

__device__ __forceinline__ uint32_t smem_u32(const void* p) {
    return (uint32_t)__cvta_generic_to_shared(p);
}
__device__ __forceinline__ uint32_t pack_bf16(__nv_bfloat16 a, __nv_bfloat16 b) {
    __nv_bfloat162 t = __halves2bfloat162(a, b);   // .x = a (low halfword)
    uint32_t u; memcpy(&u, &t, 4); return u;
}
#define LDSM_X4(r0, r1, r2, r3, addr) \
    asm volatile("ldmatrix.sync.aligned.m8n8.x4.shared.b16 {%0,%1,%2,%3}, [%4];" \
        : "=r"(r0), "=r"(r1), "=r"(r2), "=r"(r3) : "r"(addr))
#define LDSM_X4T(r0, r1, r2, r3, addr) \
    asm volatile("ldmatrix.sync.aligned.m8n8.x4.trans.shared.b16 {%0,%1,%2,%3}, [%4];" \
        : "=r"(r0), "=r"(r1), "=r"(r2), "=r"(r3) : "r"(addr))
#define MMA_BF16(c, a0, a1, a2, a3, b0, b1) \
    asm volatile("mma.sync.aligned.m16n8k16.row.col.f32.bf16.bf16.f32 " \
        "{%0,%1,%2,%3}, {%4,%5,%6,%7}, {%8,%9}, {%0,%1,%2,%3};" \
        : "+f"((c)[0]), "+f"((c)[1]), "+f"((c)[2]), "+f"((c)[3]) \
        : "r"(a0), "r"(a1), "r"(a2), "r"(a3), "r"(b0), "r"(b1))

__global__ __launch_bounds__(THREADS, 1)
void selattn_kernel(const float* __restrict__ q, const float* __restrict__ k,
                    const float* __restrict__ v, const int* __restrict__ sidx,
                    const int* __restrict__ slp, float* __restrict__ out) {
    extern __shared__ char shraw[];
    char* sm = (char*)(((uintptr_t)shraw + 1023) & ~(uintptr_t)1023);
    float* ls  = (float*)(sm + LS_OFF);
    unsigned* selm = (unsigned*)(sm + SELM_OFF);
    int* jlist = (int*)(sm + JL_OFF);
    int* njsp  = (int*)(sm + NJS_OFF);

    const int S    = slp ? slp[0] : 2048;
    const int qt   = blockIdx.x;
    const int h    = blockIdx.y;
    const int g    = h >> 2;
    const int t0   = qt * QT;
    const int seq0 = (t0 / S) * S;
    const int tid  = threadIdx.x;
    const int lane = tid & 31;
    const int w    = tid >> 5;

    // ---- selection masks / jlist / ls init ----
    if (tid < QT) { selm[tid] = 0u; ls[tid] = 0.0f; }
    __syncthreads();
    for (int f = tid; f < QT * TOPK; f += THREADS) {
        int qi = f >> 4, kk = f & 15;
        int b = sidx[(size_t)(t0 + qi) * (GRP * TOPK) + g * TOPK + kk] & 31;
        atomicOr(&selm[qi], 1u << b);
    }
    __syncthreads();
    if (tid < QT) {
        int tq = (t0 + tid) - seq0;
        int bt = tq >> 6;
        unsigned causal = (bt >= 31) ? 0xffffffffu : ((1u << (bt + 1)) - 1u);
        selm[tid] &= causal;
    }
    __syncthreads();
    if (tid == 0) {
        unsigned u = 0;
        #pragma unroll
        for (int i = 0; i < QT; i++) u |= selm[i];
        int n = 0;
        for (int j = 0; j < NBITS; j++)
            if ((u >> j) & 1u) jlist[n++] = j;
        *njsp = n;
    }
    __syncthreads();
    const int njs = *njsp;

    // ---- Q/K hi/lo bf16 fill: [64][784], hi cols 0-191, lo 192-383 ----
    auto fill_tile = [&](char* dst, const float* grow, size_t rstride,
                         int tl, int nth) {
        for (int f = tl; f < 64 * 96; f += nth) {
            int r = f / 96, dp = f - r * 96;
            int d = dp * 2;
            float2 kv = *(const float2*)(grow + (size_t)r * rstride + d);
            __nv_bfloat16 h0 = __float2bfloat16(kv.x);
            __nv_bfloat16 h1 = __float2bfloat16(kv.y);
            __nv_bfloat16 l0 = __float2bfloat16(kv.x - __bfloat162float(h0));
            __nv_bfloat16 l1 = __float2bfloat16(kv.y - __bfloat162float(h1));
            char* row = dst + (size_t)r * (XROW * 2);
            *(uint32_t*)(row + d * 2)         = pack_bf16(h0, h1);
            *(uint32_t*)(row + (192 + d) * 2) = pack_bf16(l0, l1);
        }
    };
    // ---- V hi/lo bf16 fill: vx[s][dh 256B | dl 256B], coalesced ----
    auto fill_vx = [&](const float* vblk, int tl, int nth) {
        for (int f = tl; f < 64 * 32; f += nth) {
            int s = f >> 5, c = f & 31;
            float4 vv = ((const float4*)vblk)[(size_t)s * HQ * (DV / 4) + c];
            __nv_bfloat16 h0 = __float2bfloat16(vv.x);
            __nv_bfloat16 h1 = __float2bfloat16(vv.y);
            __nv_bfloat16 h2 = __float2bfloat16(vv.z);
            __nv_bfloat16 h3 = __float2bfloat16(vv.w);
            __nv_bfloat16 l0 = __float2bfloat16(vv.x - __bfloat162float(h0));
            __nv_bfloat16 l1 = __float2bfloat16(vv.y - __bfloat162float(h1));
            __nv_bfloat16 l2 = __float2bfloat16(vv.z - __bfloat162float(h2));
            __nv_bfloat16 l3 = __float2bfloat16(vv.w - __bfloat162float(h3));
            char* row = sm + VX_OFF + (size_t)s * VXP;
            *(uint32_t*)(row + c * 8)           = pack_bf16(h0, h1);
            *(uint32_t*)(row + c * 8 + 4)       = pack_bf16(h2, h3);
            *(uint32_t*)(row + 256 + c * 8)     = pack_bf16(l0, l1);
            *(uint32_t*)(row + 256 + c * 8 + 4) = pack_bf16(l2, l3);
        }
    };

    // ---- prologue fills ----
    fill_tile(sm + QX_OFF, q + (size_t)t0 * HQ * DQK + (size_t)h * DQK,
              (size_t)HQ * DQK, tid, THREADS);
    {
        const int j0 = jlist[0];
        fill_tile(sm + KX0_OFF, k + ((size_t)(seq0 + j0 * 64) * HQ + h) * DQK,
                  (size_t)HQ * DQK, tid, THREADS);
        if (njs > 1) {
            const int j1 = jlist[1];
            fill_tile(sm + KX1_OFF, k + ((size_t)(seq0 + j1 * 64) * HQ + h) * DQK,
                      (size_t)HQ * DQK, tid, THREADS);
        }
        fill_vx(v + ((size_t)(seq0 + jlist[0] * 64) * HQ + h) * DV, tid, THREADS);
    }
    __syncthreads();

    if (w < 8) {
        // ===== SCORE GROUP (w0-7): fused 3-term HMMA + bf16 hi/lo P output =====
        const int m0    = (w >> 1) * 16;
        const int nhalf = (w & 1) * 32;
        const uint32_t qx_base = smem_u32(sm + QX_OFF)
            + (uint32_t)(m0 + (lane & 15)) * (XROW * 2) + (uint32_t)((lane >> 4) << 4);
        const uint32_t kb_row = (uint32_t)(nhalf + (lane & 7) + ((lane >> 4) << 3)) * (XROW * 2)
                              + (uint32_t)(((lane >> 3) & 1) << 4);
        const int r0 = m0 + (lane >> 2);
        const int r1 = r0 + 8;
        const int tq0 = t0 + r0 - seq0;
        const int tq1 = t0 + r1 - seq0;
        const int st256 = tid;

        unsigned wsel = 0;
        #pragma unroll
        for (int i = 0; i < 16; i++) wsel |= selm[m0 + i];

        for (int ii = 0; ii < njs; ii++) {
            const int b = ii & 1;
            const int j = jlist[ii];
            BAR_SYNC(EMPTY0 + b, 512);            // ps[b] free
            char* ps = sm + (b ? PS1_OFF : PS0_OFF);

            if ((wsel >> j) & 1u) {
                const uint32_t kx = smem_u32(sm + (b ? KX1_OFF : KX0_OFF));
                float c[4][4];
                #pragma unroll
                for (int nt = 0; nt < 4; nt++)
                    #pragma unroll
                    for (int i = 0; i < 4; i++) c[nt][i] = 0.0f;

                #pragma unroll 2
                for (int st = 0; st < 12; st++) {
                    const uint32_t koff = (uint32_t)st * 32;
                    uint32_t ah0, ah1, ah2, ah3, al0, al1, al2, al3;
                    LDSM_X4(ah0, ah1, ah2, ah3, qx_base + koff);
                    LDSM_X4(al0, al1, al2, al3, qx_base + LOOFF + koff);
                    uint32_t bh00, bh01, bh10, bh11, bh20, bh21, bh30, bh31;
                    LDSM_X4(bh00, bh01, bh10, bh11, kx + kb_row + koff);
                    LDSM_X4(bh20, bh21, bh30, bh31, kx + kb_row + ROW16 + koff);
                    uint32_t bl00, bl01, bl10, bl11, bl20, bl21, bl30, bl31;
                    LDSM_X4(bl00, bl01, bl10, bl11, kx + kb_row + LOOFF + koff);
                    LDSM_X4(bl20, bl21, bl30, bl31, kx + kb_row + ROW16 + LOOFF + koff);
                    MMA_BF16(c[0], ah0, ah1, ah2, ah3, bh00, bh01);
                    MMA_BF16(c[1], ah0, ah1, ah2, ah3, bh10, bh11);
                    MMA_BF16(c[2], ah0, ah1, ah2, ah3, bh20, bh21);
                    MMA_BF16(c[3], ah0, ah1, ah2, ah3, bh30, bh31);
                    MMA_BF16(c[0], ah0, ah1, ah2, ah3, bl00, bl01);
                    MMA_BF16(c[1], ah0, ah1, ah2, ah3, bl10, bl11);
                    MMA_BF16(c[2], ah0, ah1, ah2, ah3, bl20, bl21);
                    MMA_BF16(c[3], ah0, ah1, ah2, ah3, bl30, bl31);
                    MMA_BF16(c[0], al0, al1, al2, al3, bh00, bh01);
                    MMA_BF16(c[1], al0, al1, al2, al3, bh10, bh11);
                    MMA_BF16(c[2], al0, al1, al2, al3, bh20, bh21);
                    MMA_BF16(c[3], al0, al1, al2, al3, bh30, bh31);
                }

                const unsigned sel0 = (selm[r0] >> j) & 1u;
                const unsigned sel1 = (selm[r1] >> j) & 1u;
                float rsum0 = 0.0f, rsum1 = 0.0f;
                #pragma unroll
                for (int nt = 0; nt < 4; nt++) {
                    const int col = nhalf + nt * 8 + 2 * (lane & 3);
                    const int gc0 = j * 64 + col;
                    float p00 = (sel0 && gc0     <= tq0) ? __expf(c[nt][0] * SMSCALE) : 0.0f;
                    float p01 = (sel0 && gc0 + 1 <= tq0) ? __expf(c[nt][1] * SMSCALE) : 0.0f;
                    float p10 = (sel1 && gc0     <= tq1) ? __expf(c[nt][2] * SMSCALE) : 0.0f;
                    float p11 = (sel1 && gc0 + 1 <= tq1) ? __expf(c[nt][3] * SMSCALE) : 0.0f;
                    rsum0 += p00 + p01;
                    rsum1 += p10 + p11;
                    // hi/lo split, pack pairs, store
                    __nv_bfloat16 h00 = __float2bfloat16(p00);
                    __nv_bfloat16 h01 = __float2bfloat16(p01);
                    __nv_bfloat16 h10 = __float2bfloat16(p10);
                    __nv_bfloat16 h11 = __float2bfloat16(p11);
                    __nv_bfloat16 l00 = __float2bfloat16(p00 - __bfloat162float(h00));
                    __nv_bfloat16 l01 = __float2bfloat16(p01 - __bfloat162float(h01));
                    __nv_bfloat16 l10 = __float2bfloat16(p10 - __bfloat162float(h10));
                    __nv_bfloat16 l11 = __float2bfloat16(p11 - __bfloat162float(h11));
                    char* pr0 = ps + r0 * PSP + col * 2;
                    char* pr1 = ps + r1 * PSP + col * 2;
                    *(uint32_t*)(pr0)       = pack_bf16(h00, h01);
                    *(uint32_t*)(pr1)       = pack_bf16(h10, h11);
                    *(uint32_t*)(pr0 + 128) = pack_bf16(l00, l01);
                    *(uint32_t*)(pr1 + 128) = pack_bf16(l10, l11);
                }
                rsum0 += __shfl_xor_sync(0xffffffffu, rsum0, 1);
                rsum0 += __shfl_xor_sync(0xffffffffu, rsum0, 2);
                rsum1 += __shfl_xor_sync(0xffffffffu, rsum1, 1);
                rsum1 += __shfl_xor_sync(0xffffffffu, rsum1, 2);
                if ((lane & 3) == 0) {
                    atomicAdd(&ls[r0], rsum0);
                    atomicAdd(&ls[r1], rsum1);
                }
            } else {
                #pragma unroll
                for (int nt = 0; nt < 4; nt++) {
                    const int col = nhalf + nt * 8 + 2 * (lane & 3);
                    char* pr0 = ps + r0 * PSP + col * 2;
                    char* pr1 = ps + r1 * PSP + col * 2;
                    *(uint32_t*)(pr0)       = 0u;
                    *(uint32_t*)(pr1)       = 0u;
                    *(uint32_t*)(pr0 + 128) = 0u;
                    *(uint32_t*)(pr1 + 128) = 0u;
                }
            }
            MEMBAR_CTA();
            BAR_ARRIVE(FULL0 + b, 512);           // ps[b] ready for PV
            BAR_SYNC(SBAR, 256);                  // score warps done reading kx[b]
            if (ii + 2 < njs) {
                const int jn = jlist[ii + 2];
                fill_tile(sm + (b ? KX1_OFF : KX0_OFF),
                          k + ((size_t)(seq0 + jn * 64) * HQ + h) * DQK,
                          (size_t)HQ * DQK, st256, 256);
            }
        }
        BAR_SYNC(EMPTY0 + (njs & 1), 512);
        BAR_SYNC(EMPTY0 + ((njs + 1) & 1), 512);
        __syncthreads();
    } else {
        // ===== PV GROUP (w8-15): HMMA P x V, O in fragments =====
        const int pt = tid - 256;
        const int pw = w - 8;
        const int qb = (pw & 3) * 16;             // warp's 16 query rows
        const int db = (pw >> 2) * 64;            // warp's 64 dims
        const uint32_t ps_lane = (uint32_t)((qb + (lane & 15)) * PSP + ((lane >> 4) << 4));
        const uint32_t vx_lane = smem_u32(sm + VX_OFF)
            + (uint32_t)((lane & 15) * VXP + ((lane >> 4) << 4));
        float c[8][4];
        #pragma unroll
        for (int nt = 0; nt < 8; nt++)
            #pragma unroll
            for (int i = 0; i < 4; i++) c[nt][i] = 0.0f;

        BAR_ARRIVE(EMPTY0, 512);
        BAR_ARRIVE(EMPTY0 + 1, 512);

        for (int ii = 0; ii < njs; ii++) {
            const int b = ii & 1;
            BAR_SYNC(FULL0 + b, 512);             // ps[b] ready; vx fill visible
            const uint32_t psx = smem_u32(sm + (b ? PS1_OFF : PS0_OFF)) + ps_lane;
            #pragma unroll
            for (int ks = 0; ks < 4; ks++) {
                uint32_t ph0, ph1, ph2, ph3, pl0, pl1, pl2, pl3;
                LDSM_X4(ph0, ph1, ph2, ph3, psx + (uint32_t)ks * 32);
                LDSM_X4(pl0, pl1, pl2, pl3, psx + 128 + (uint32_t)ks * 32);
                const uint32_t vrow = vx_lane + (uint32_t)(ks * 16) * VXP;
                #pragma unroll
                for (int dt = 0; dt < 4; dt++) {
                    const uint32_t dof = (uint32_t)(db + dt * 16) * 2;
                    uint32_t vh0, vh1, vh2, vh3, vl0, vl1, vl2, vl3;
                    LDSM_X4T(vh0, vh1, vh2, vh3, vrow + dof);
                    LDSM_X4T(vl0, vl1, vl2, vl3, vrow + 256 + dof);
                    MMA_BF16(c[2 * dt],     ph0, ph1, ph2, ph3, vh0, vh1);
                    MMA_BF16(c[2 * dt + 1], ph0, ph1, ph2, ph3, vh2, vh3);
                    MMA_BF16(c[2 * dt],     ph0, ph1, ph2, ph3, vl0, vl1);
                    MMA_BF16(c[2 * dt + 1], ph0, ph1, ph2, ph3, vl2, vl3);
                    MMA_BF16(c[2 * dt],     pl0, pl1, pl2, pl3, vh0, vh1);
                    MMA_BF16(c[2 * dt + 1], pl0, pl1, pl2, pl3, vh2, vh3);
                }
            }
            BAR_SYNC(PBAR, 256);                  // PV warps done with ps[b]/vx
            BAR_ARRIVE(EMPTY0 + b, 512);
            if (ii + 1 < njs) {
                const int jn = jlist[ii + 1];
                fill_vx(v + ((size_t)(seq0 + jn * 64) * HQ + h) * DV, pt, 256);
            }
        }
        __syncthreads();
        // epilogue: scale fragments by 1/ls and store
        const int gr = lane >> 2;
        const int gc = lane & 3;
        const int r0 = qb + gr, r1 = r0 + 8;
        const float il0 = 1.0f / ls[r0];
        const float il1 = 1.0f / ls[r1];
        #pragma unroll
        for (int nt = 0; nt < 8; nt++) {
            const int d0 = db + nt * 8 + 2 * gc;
            float2 o0 = make_float2(c[nt][0] * il0, c[nt][1] * il0);
            float2 o1 = make_float2(c[nt][2] * il1, c[nt][3] * il1);
            *(float2*)(out + (size_t)(t0 + r0) * (HQ * DV) + (size_t)h * DV + d0) = o0;
            *(float2*)(out + (size_t)(t0 + r1) * (HQ * DV) + (size_t)h * DV + d0) = o1;
        }
        return;
    }
}

extern "C" void kernel_launch(void* const* d_in, const int* in_sizes, int n_in,
                              void* d_out, int out_size) {
    const float* q   = (const float*)d_in[0];
    const float* k   = (const float*)d_in[1];
    const float* v   = (const float*)d_in[2];
    const int*   idx = (const int*)d_in[3];
    const int*   slp = (n_in >= 6) ? (const int*)d_in[5] : nullptr;
    float* out = (float*)d_out;

    const int T = in_sizes[0] / (HQ * DQK);

    static bool attr_set = false;
    if (!attr_set) {
        cudaFuncSetAttribute(selattn_kernel,
                             cudaFuncAttributeMaxDynamicSharedMemorySize, SMEM_BYTES);
        attr_set = true;
    }

    dim3 grid(T / QT, HQ);
    selattn_kernel<<<grid, THREADS, SMEM_BYTES>>>(q, k, v, idx, slp, out);
}

// round 17
// speedup vs baseline: 4.3350x; 1.4309x over previous
#include <cuda_runtime.h>
#include <cuda_bf16.h>
#include <cstdint>
#include <stdint.h>
#include <math.h>
#include <string.h>

#define HQ 16
#define GRP 4
#define TOPK 16
#define DQK 192
#define DV 128
#define QT 64
#define THREADS 512
#define NBITS 32
#define SMSCALE 0.07216878364870322f
#define XROW 392              // Q/K bf16 row: 384 data + 8 pad (784B = 49*16)
#define ROW16 (16 * XROW * 2)
#define LOOFF 384u            // Q/K lo-half byte offset
#define PSP 272               // ps row pitch bytes: 128 ph | 128 pl | 16 pad
#define VXP 528               // vx row pitch bytes: 256 vh | 256 vl | 16 pad

#define QX_OFF   0            // [64][784]  = 50176
#define KX0_OFF  50176
#define KX1_OFF  100352
#define VX_OFF   150528       // [64][528]  = 33792
#define PS0_OFF  184320       // [64][272]  = 17408
#define PS1_OFF  201728
#define LS_OFF   219136       // [64] f32
#define SELM_OFF 219392       // [64] u32
#define JL_OFF   219648       // [33] int
#define NJS_OFF  219780
#define SMEM_BYTES (219784 + 1024)

#define FULL0  1
#define EMPTY0 3
#define SBAR   5
#define PBAR   6
#define KB0    7
#define BAR_SYNC(id, cnt)   asm volatile("bar.sync %0, %1;"   :: "r"(id), "r"(cnt) : "memory")
#define BAR_ARRIVE(id, cnt) asm volatile("bar.arrive %0, %1;" :: "r"(id), "r"(cnt) : "memory")

__device__ __forceinline__ uint32_t smem_u32(const void* p) {
    return (uint32_t)__cvta_generic_to_shared(p);
}
__device__ __forceinline__ uint32_t pack_bf16(__nv_bfloat16 a, __nv_bfloat16 b) {
    __nv_bfloat162 t = __halves2bfloat162(a, b);
    uint32_t u; memcpy(&u, &t, 4); return u;
}
// convert float4 -> (hi u64, lo u64) bf16 pairs
__device__ __forceinline__ void split4(const float4 v, uint64_t& hi, uint64_t& lo) {
    __nv_bfloat16 h0 = __float2bfloat16(v.x), h1 = __float2bfloat16(v.y);
    __nv_bfloat16 h2 = __float2bfloat16(v.z), h3 = __float2bfloat16(v.w);
    __nv_bfloat16 l0 = __float2bfloat16(v.x - __bfloat162float(h0));
    __nv_bfloat16 l1 = __float2bfloat16(v.y - __bfloat162float(h1));
    __nv_bfloat16 l2 = __float2bfloat16(v.z - __bfloat162float(h2));
    __nv_bfloat16 l3 = __float2bfloat16(v.w - __bfloat162float(h3));
    hi = (uint64_t)pack_bf16(h0, h1) | ((uint64_t)pack_bf16(h2, h3) << 32);
    lo = (uint64_t)pack_bf16(l0, l1) | ((uint64_t)pack_bf16(l2, l3) << 32);
}
#define LDSM_X4(r0, r1, r2, r3, addr) \
    asm volatile("ldmatrix.sync.aligned.m8n8.x4.shared.b16 {%0,%1,%2,%3}, [%4];" \
        : "=r"(r0), "=r"(r1), "=r"(r2), "=r"(r3) : "r"(addr))
#define LDSM_X4T(r0, r1, r2, r3, addr) \
    asm volatile("ldmatrix.sync.aligned.m8n8.x4.trans.shared.b16 {%0,%1,%2,%3}, [%4];" \
        : "=r"(r0), "=r"(r1), "=r"(r2), "=r"(r3) : "r"(addr))
#define MMA_BF16(c, a0, a1, a2, a3, b0, b1) \
    asm volatile("mma.sync.aligned.m16n8k16.row.col.f32.bf16.bf16.f32 " \
        "{%0,%1,%2,%3}, {%4,%5,%6,%7}, {%8,%9}, {%0,%1,%2,%3};" \
        : "+f"((c)[0]), "+f"((c)[1]), "+f"((c)[2]), "+f"((c)[3]) \
        : "r"(a0), "r"(a1), "r"(a2), "r"(a3), "r"(b0), "r"(b1))

__global__ __launch_bounds__(THREADS, 1)
void selattn_kernel(const float* __restrict__ q, const float* __restrict__ k,
                    const float* __restrict__ v, const int* __restrict__ sidx,
                    const int* __restrict__ slp, float* __restrict__ out) {
    extern __shared__ char shraw[];
    char* sm = (char*)(((uintptr_t)shraw + 1023) & ~(uintptr_t)1023);
    float* ls  = (float*)(sm + LS_OFF);
    unsigned* selm = (unsigned*)(sm + SELM_OFF);
    int* jlist = (int*)(sm + JL_OFF);
    int* njsp  = (int*)(sm + NJS_OFF);

    const int S    = slp ? slp[0] : 2048;
    const int qt   = blockIdx.x;
    const int h    = blockIdx.y;
    const int g    = h >> 2;
    const int t0   = qt * QT;
    const int seq0 = (t0 / S) * S;
    const int tid  = threadIdx.x;
    const int lane = tid & 31;
    const int w    = tid >> 5;

    // ---- selection masks / jlist / ls init ----
    if (tid < QT) { selm[tid] = 0u; ls[tid] = 0.0f; }
    __syncthreads();
    for (int f = tid; f < QT * TOPK; f += THREADS) {
        int qi = f >> 4, kk = f & 15;
        int b = sidx[(size_t)(t0 + qi) * (GRP * TOPK) + g * TOPK + kk] & 31;
        atomicOr(&selm[qi], 1u << b);
    }
    __syncthreads();
    if (tid < QT) {
        int tq = (t0 + tid) - seq0;
        int bt = tq >> 6;
        unsigned causal = (bt >= 31) ? 0xffffffffu : ((1u << (bt + 1)) - 1u);
        selm[tid] &= causal;
    }
    __syncthreads();
    if (tid == 0) {
        unsigned u = 0;
        #pragma unroll
        for (int i = 0; i < QT; i++) u |= selm[i];
        int n = 0;
        for (int j = 0; j < NBITS; j++)
            if ((u >> j) & 1u) jlist[n++] = j;
        *njsp = n;
    }
    __syncthreads();
    const int njs = *njsp;

    // ---- full-tile fill (prologue): float4 loads, u64 stores ----
    auto fill_tile4 = [&](char* dst, const float* grow, int tl, int nth) {
        for (int f = tl; f < 64 * 48; f += nth) {
            int r = f / 48, d = (f % 48) * 4;
            float4 kv = *(const float4*)(grow + (size_t)r * HQ * DQK + d);
            uint64_t hi, lo; split4(kv, hi, lo);
            char* row = dst + (size_t)r * (XROW * 2);
            *(uint64_t*)(row + d * 2)       = hi;
            *(uint64_t*)(row + 384 + d * 2) = lo;
        }
    };
    auto fill_vx = [&](const float* vblk, int tl, int nth) {
        for (int f = tl; f < 64 * 32; f += nth) {
            int s = f >> 5, c = f & 31;
            float4 vv = ((const float4*)vblk)[(size_t)s * HQ * (DV / 4) + c];
            uint64_t hi, lo; split4(vv, hi, lo);
            char* row = sm + VX_OFF + (size_t)s * VXP;
            *(uint64_t*)(row + c * 8)       = hi;
            *(uint64_t*)(row + 256 + c * 8) = lo;
        }
    };

    // ---- prologue fills ----
    fill_tile4(sm + QX_OFF, q + (size_t)t0 * HQ * DQK + (size_t)h * DQK, tid, THREADS);
    {
        fill_tile4(sm + KX0_OFF,
                   k + ((size_t)(seq0 + jlist[0] * 64) * HQ + h) * DQK, tid, THREADS);
        if (njs > 1)
            fill_tile4(sm + KX1_OFF,
                       k + ((size_t)(seq0 + jlist[1] * 64) * HQ + h) * DQK, tid, THREADS);
        fill_vx(v + ((size_t)(seq0 + jlist[0] * 64) * HQ + h) * DV, tid, THREADS);
    }
    __syncthreads();

    if (w < 8) {
        // ===== SCORE GROUP (w0-7): 3-term HMMA + prefetched half K-fill =====
        const int m0    = (w >> 1) * 16;
        const int nhalf = (w & 1) * 32;
        const uint32_t qx_base = smem_u32(sm + QX_OFF)
            + (uint32_t)(m0 + (lane & 15)) * (XROW * 2) + (uint32_t)((lane >> 4) << 4);
        const uint32_t kb_row = (uint32_t)(nhalf + (lane & 7) + ((lane >> 4) << 3)) * (XROW * 2)
                              + (uint32_t)(((lane >> 3) & 1) << 4);
        const int r0 = m0 + (lane >> 2);
        const int r1 = r0 + 8;
        const int tq0 = t0 + r0 - seq0;
        const int tq1 = t0 + r1 - seq0;

        unsigned wsel = 0;
        #pragma unroll
        for (int i = 0; i < 16; i++) wsel |= selm[m0 + i];

        for (int ii = 0; ii < njs; ii++) {
            const int b = ii & 1;
            const int j = jlist[ii];
            const bool pf = (ii + 2 < njs);
            float4 kreg[6];
            if (pf) {
                const float* kb2 = k + ((size_t)(seq0 + jlist[ii + 2] * 64) * HQ + h) * DQK;
                #pragma unroll
                for (int u = 0; u < 6; u++) {
                    int f = tid + u * 256;             // rows 0..31
                    int r = f / 48, d = (f % 48) * 4;
                    kreg[u] = *(const float4*)(kb2 + (size_t)r * HQ * DQK + d);
                }
            }
            BAR_SYNC(EMPTY0 + b, 512);            // ps[b] free; kx[b] refilled
            char* ps = sm + (b ? PS1_OFF : PS0_OFF);

            if ((wsel >> j) & 1u) {
                const uint32_t kx = smem_u32(sm + (b ? KX1_OFF : KX0_OFF));
                float c[4][4];
                #pragma unroll
                for (int nt = 0; nt < 4; nt++)
                    #pragma unroll
                    for (int i = 0; i < 4; i++) c[nt][i] = 0.0f;

                #pragma unroll 2
                for (int st = 0; st < 12; st++) {
                    const uint32_t koff = (uint32_t)st * 32;
                    uint32_t ah0, ah1, ah2, ah3, al0, al1, al2, al3;
                    LDSM_X4(ah0, ah1, ah2, ah3, qx_base + koff);
                    LDSM_X4(al0, al1, al2, al3, qx_base + LOOFF + koff);
                    uint32_t bh00, bh01, bh10, bh11, bh20, bh21, bh30, bh31;
                    LDSM_X4(bh00, bh01, bh10, bh11, kx + kb_row + koff);
                    LDSM_X4(bh20, bh21, bh30, bh31, kx + kb_row + ROW16 + koff);
                    uint32_t bl00, bl01, bl10, bl11, bl20, bl21, bl30, bl31;
                    LDSM_X4(bl00, bl01, bl10, bl11, kx + kb_row + LOOFF + koff);
                    LDSM_X4(bl20, bl21, bl30, bl31, kx + kb_row + ROW16 + LOOFF + koff);
                    MMA_BF16(c[0], ah0, ah1, ah2, ah3, bh00, bh01);
                    MMA_BF16(c[1], ah0, ah1, ah2, ah3, bh10, bh11);
                    MMA_BF16(c[2], ah0, ah1, ah2, ah3, bh20, bh21);
                    MMA_BF16(c[3], ah0, ah1, ah2, ah3, bh30, bh31);
                    MMA_BF16(c[0], ah0, ah1, ah2, ah3, bl00, bl01);
                    MMA_BF16(c[1], ah0, ah1, ah2, ah3, bl10, bl11);
                    MMA_BF16(c[2], ah0, ah1, ah2, ah3, bl20, bl21);
                    MMA_BF16(c[3], ah0, ah1, ah2, ah3, bl30, bl31);
                    MMA_BF16(c[0], al0, al1, al2, al3, bh00, bh01);
                    MMA_BF16(c[1], al0, al1, al2, al3, bh10, bh11);
                    MMA_BF16(c[2], al0, al1, al2, al3, bh20, bh21);
                    MMA_BF16(c[3], al0, al1, al2, al3, bh30, bh31);
                }

                const unsigned sel0 = (selm[r0] >> j) & 1u;
                const unsigned sel1 = (selm[r1] >> j) & 1u;
                float rsum0 = 0.0f, rsum1 = 0.0f;
                #pragma unroll
                for (int nt = 0; nt < 4; nt++) {
                    const int col = nhalf + nt * 8 + 2 * (lane & 3);
                    const int gc0 = j * 64 + col;
                    float p00 = (sel0 && gc0     <= tq0) ? __expf(c[nt][0] * SMSCALE) : 0.0f;
                    float p01 = (sel0 && gc0 + 1 <= tq0) ? __expf(c[nt][1] * SMSCALE) : 0.0f;
                    float p10 = (sel1 && gc0     <= tq1) ? __expf(c[nt][2] * SMSCALE) : 0.0f;
                    float p11 = (sel1 && gc0 + 1 <= tq1) ? __expf(c[nt][3] * SMSCALE) : 0.0f;
                    rsum0 += p00 + p01;
                    rsum1 += p10 + p11;
                    __nv_bfloat16 h00 = __float2bfloat16(p00);
                    __nv_bfloat16 h01 = __float2bfloat16(p01);
                    __nv_bfloat16 h10 = __float2bfloat16(p10);
                    __nv_bfloat16 h11 = __float2bfloat16(p11);
                    __nv_bfloat16 l00 = __float2bfloat16(p00 - __bfloat162float(h00));
                    __nv_bfloat16 l01 = __float2bfloat16(p01 - __bfloat162float(h01));
                    __nv_bfloat16 l10 = __float2bfloat16(p10 - __bfloat162float(h10));
                    __nv_bfloat16 l11 = __float2bfloat16(p11 - __bfloat162float(h11));
                    char* pr0 = ps + r0 * PSP + col * 2;
                    char* pr1 = ps + r1 * PSP + col * 2;
                    *(uint32_t*)(pr0)       = pack_bf16(h00, h01);
                    *(uint32_t*)(pr1)       = pack_bf16(h10, h11);
                    *(uint32_t*)(pr0 + 128) = pack_bf16(l00, l01);
                    *(uint32_t*)(pr1 + 128) = pack_bf16(l10, l11);
                }
                rsum0 += __shfl_xor_sync(0xffffffffu, rsum0, 1);
                rsum0 += __shfl_xor_sync(0xffffffffu, rsum0, 2);
                rsum1 += __shfl_xor_sync(0xffffffffu, rsum1, 1);
                rsum1 += __shfl_xor_sync(0xffffffffu, rsum1, 2);
                if ((lane & 3) == 0) {
                    atomicAdd(&ls[r0], rsum0);
                    atomicAdd(&ls[r1], rsum1);
                }
            } else {
                #pragma unroll
                for (int nt = 0; nt < 4; nt++) {
                    const int col = nhalf + nt * 8 + 2 * (lane & 3);
                    char* pr0 = ps + r0 * PSP + col * 2;
                    char* pr1 = ps + r1 * PSP + col * 2;
                    *(uint32_t*)(pr0)       = 0u;
                    *(uint32_t*)(pr1)       = 0u;
                    *(uint32_t*)(pr0 + 128) = 0u;
                    *(uint32_t*)(pr1 + 128) = 0u;
                }
            }
            BAR_ARRIVE(FULL0 + b, 512);           // ps[b] ready (bar release fence)
            BAR_SYNC(SBAR, 256);                  // score warps done reading kx[b]
            if (pf) {
                BAR_ARRIVE(KB0 + b, 512);         // tell PV: kx[b] free to refill
                char* kxd = sm + (b ? KX1_OFF : KX0_OFF);
                #pragma unroll
                for (int u = 0; u < 6; u++) {
                    int f = tid + u * 256;
                    int r = f / 48, d = (f % 48) * 4;
                    uint64_t hi, lo; split4(kreg[u], hi, lo);
                    char* row = kxd + (size_t)r * (XROW * 2);
                    *(uint64_t*)(row + d * 2)       = hi;
                    *(uint64_t*)(row + 384 + d * 2) = lo;
                }
            }
        }
        BAR_SYNC(EMPTY0 + (njs & 1), 512);
        BAR_SYNC(EMPTY0 + ((njs + 1) & 1), 512);
        __syncthreads();
    } else {
        // ===== PV GROUP (w8-15): HMMA P x V + half K-fill + V-fill =====
        const int pt = tid - 256;
        const int pw = w - 8;
        const int qb = (pw & 3) * 16;
        const int db = (pw >> 2) * 64;
        const uint32_t ps_lane = (uint32_t)((qb + (lane & 15)) * PSP + ((lane >> 4) << 4));
        const uint32_t vx_lane = smem_u32(sm + VX_OFF)
            + (uint32_t)((lane & 15) * VXP + ((lane >> 4) << 4));
        float c[8][4];
        #pragma unroll
        for (int nt = 0; nt < 8; nt++)
            #pragma unroll
            for (int i = 0; i < 4; i++) c[nt][i] = 0.0f;

        BAR_ARRIVE(EMPTY0, 512);
        BAR_ARRIVE(EMPTY0 + 1, 512);

        for (int ii = 0; ii < njs; ii++) {
            const int b = ii & 1;
            const bool pf = (ii + 2 < njs);
            float4 kreg[6];
            if (pf) {
                const float* kb2 = k + ((size_t)(seq0 + jlist[ii + 2] * 64) * HQ + h) * DQK;
                #pragma unroll
                for (int u = 0; u < 6; u++) {
                    int f = pt + u * 256;              // rows 32..63
                    int r = 32 + f / 48, d = (f % 48) * 4;
                    kreg[u] = *(const float4*)(kb2 + (size_t)r * HQ * DQK + d);
                }
            }
            BAR_SYNC(FULL0 + b, 512);             // ps[b] ready
            const uint32_t psx = smem_u32(sm + (b ? PS1_OFF : PS0_OFF)) + ps_lane;
            #pragma unroll
            for (int ks = 0; ks < 4; ks++) {
                uint32_t ph0, ph1, ph2, ph3, pl0, pl1, pl2, pl3;
                LDSM_X4(ph0, ph1, ph2, ph3, psx + (uint32_t)ks * 32);
                LDSM_X4(pl0, pl1, pl2, pl3, psx + 128 + (uint32_t)ks * 32);
                const uint32_t vrow = vx_lane + (uint32_t)(ks * 16) * VXP;
                #pragma unroll
                for (int dt = 0; dt < 4; dt++) {
                    const uint32_t dof = (uint32_t)(db + dt * 16) * 2;
                    uint32_t vh0, vh1, vh2, vh3, vl0, vl1, vl2, vl3;
                    LDSM_X4T(vh0, vh1, vh2, vh3, vrow + dof);
                    LDSM_X4T(vl0, vl1, vl2, vl3, vrow + 256 + dof);
                    MMA_BF16(c[2 * dt],     ph0, ph1, ph2, ph3, vh0, vh1);
                    MMA_BF16(c[2 * dt + 1], ph0, ph1, ph2, ph3, vh2, vh3);
                    MMA_BF16(c[2 * dt],     ph0, ph1, ph2, ph3, vl0, vl1);
                    MMA_BF16(c[2 * dt + 1], ph0, ph1, ph2, ph3, vl2, vl3);
                    MMA_BF16(c[2 * dt],     pl0, pl1, pl2, pl3, vh0, vh1);
                    MMA_BF16(c[2 * dt + 1], pl0, pl1, pl2, pl3, vh2, vh3);
                }
            }
            BAR_SYNC(PBAR, 256);                  // PV warps done with ps[b]/vx
            if (pf) {
                BAR_SYNC(KB0 + b, 512);           // score done reading kx[b]
                char* kxd = sm + (b ? KX1_OFF : KX0_OFF);
                #pragma unroll
                for (int u = 0; u < 6; u++) {
                    int f = pt + u * 256;
                    int r = 32 + f / 48, d = (f % 48) * 4;
                    uint64_t hi, lo; split4(kreg[u], hi, lo);
                    char* row = kxd + (size_t)r * (XROW * 2);
                    *(uint64_t*)(row + d * 2)       = hi;
                    *(uint64_t*)(row + 384 + d * 2) = lo;
                }
            }
            BAR_ARRIVE(EMPTY0 + b, 512);          // ps[b]+kx[b] handed back
            if (ii + 1 < njs) {
                const int jn = jlist[ii + 1];
                fill_vx(v + ((size_t)(seq0 + jn * 64) * HQ + h) * DV, pt, 256);
            }
        }
        __syncthreads();
        const int gr = lane >> 2;
        const int gc = lane & 3;
        const int r0 = qb + gr, r1 = r0 + 8;
        const float il0 = 1.0f / ls[r0];
        const float il1 = 1.0f / ls[r1];
        #pragma unroll
        for (int nt = 0; nt < 8; nt++) {
            const int d0 = db + nt * 8 + 2 * gc;
            float2 o0 = make_float2(c[nt][0] * il0, c[nt][1] * il0);
            float2 o1 = make_float2(c[nt][2] * il1, c[nt][3] * il1);
            *(float2*)(out + (size_t)(t0 + r0) * (HQ * DV) + (size_t)h * DV + d0) = o0;
            *(float2*)(out + (size_t)(t0 + r1) * (HQ * DV) + (size_t)h * DV + d0) = o1;
        }
        return;
    }
}

extern "C" void kernel_launch(void* const* d_in, const int* in_sizes, int n_in,
                              void* d_out, int out_size) {
    const float* q   = (const float*)d_in[0];
    const float* k   = (const float*)d_in[1];
    const float* v   = (const float*)d_in[2];
    const int*   idx = (const int*)d_in[3];
    const int*   slp = (n_in >= 6) ? (const int*)d_in[5] : nullptr;
    float* out = (float*)d_out;

    const int T = in_sizes[0] / (HQ * DQK);

    static bool attr_set = false;
    if (!attr_set) {
        cudaFuncSetAttribute(selattn_kernel,
                             cudaFuncAttributeMaxDynamicSharedMemorySize, SMEM_BYTES);
        attr_set = true;
    }

    dim3 grid(T / QT, HQ);
    selattn_kernel<<<grid, THREADS, SMEM_BYTES>>>(q, k, v, idx, slp, out);
}